// round 13
// baseline (speedup 1.0000x reference)
#include <cuda_runtime.h>
#include <cuda_fp16.h>
#include <cstdint>

// Problem constants (fixed shapes for this dataset)
#define BATCH   4
#define NPTS    16384
#define MPTS    4096
#define C1DIM   128
#define C2DIM   256
#define CIN     384       // C1 + C2
#define H1DIM   256
#define H2DIM   256
#define COUT    128
#define TOTAL   (BATCH * NPTS)   // 65536 points

// ---------------------------------------------------------------------------
// Scratch (static device globals — no runtime allocation allowed)
// ---------------------------------------------------------------------------
__device__ int   g_idx[TOTAL * 3];
__device__ float g_w[TOTAL * 3];
__device__ __align__(256) __half g_Xh[(size_t)TOTAL * CIN];
__device__ __align__(256) __half g_W1h[H1DIM * CIN];
__device__ __align__(256) __half g_W2h[H2DIM * H1DIM];
__device__ __align__(256) __half g_W3h[COUT * H2DIM];
__device__ __align__(256) __half g_Ann[(size_t)TOTAL * 16];        // query rows
__device__ __align__(256) __half g_Bnn[(size_t)BATCH * MPTS * 16]; // cand rows

// ---------------------------------------------------------------------------
// Small helpers
// ---------------------------------------------------------------------------
__device__ __forceinline__ uint32_t smem_to_u32(const void* p) {
    uint32_t a;
    asm("{ .reg .u64 t; cvta.to.shared.u64 t, %1; cvt.u32.u64 %0, t; }"
        : "=r"(a) : "l"(p));
    return a;
}
__device__ __forceinline__ void cpa16(uint32_t dst, const void* src) {
    asm volatile("cp.async.cg.shared.global [%0], [%1], 16;"
                 :: "r"(dst), "l"(src));
}
__device__ __forceinline__ void cpa_commit() {
    asm volatile("cp.async.commit_group;" ::: "memory");
}
template <int N>
__device__ __forceinline__ void cpa_wait() {
    asm volatile("cp.async.wait_group %0;" :: "n"(N) : "memory");
}
__device__ __forceinline__ void ldsm_x4(uint32_t* r, uint32_t addr) {
    asm volatile("ldmatrix.sync.aligned.m8n8.x4.shared.b16 {%0,%1,%2,%3}, [%4];"
                 : "=r"(r[0]), "=r"(r[1]), "=r"(r[2]), "=r"(r[3]) : "r"(addr));
}
__device__ __forceinline__ void mma_f16(float* d, const uint32_t* a,
                                        const uint32_t* b) {
    asm("mma.sync.aligned.m16n8k16.row.col.f32.f16.f16.f32 "
        "{%0,%1,%2,%3}, {%4,%5,%6,%7}, {%8,%9}, {%0,%1,%2,%3};"
        : "+f"(d[0]), "+f"(d[1]), "+f"(d[2]), "+f"(d[3])
        : "r"(a[0]), "r"(a[1]), "r"(a[2]), "r"(a[3]), "r"(b[0]), "r"(b[1]));
}
// MMA with zero C (fresh output, no accumulate)
__device__ __forceinline__ void mma_f16z(float* d, const uint32_t* a,
                                         const uint32_t* b) {
    asm("mma.sync.aligned.m16n8k16.row.col.f32.f16.f16.f32 "
        "{%0,%1,%2,%3}, {%4,%5,%6,%7}, {%8,%9}, {%10,%11,%12,%13};"
        : "=f"(d[0]), "=f"(d[1]), "=f"(d[2]), "=f"(d[3])
        : "r"(a[0]), "r"(a[1]), "r"(a[2]), "r"(a[3]), "r"(b[0]), "r"(b[1]),
          "f"(0.0f), "f"(0.0f), "f"(0.0f), "f"(0.0f));
}
__device__ __forceinline__ void sts_h2(uint32_t addr, __half a, __half b) {
    __half2 v = __halves2half2(a, b);
    asm volatile("st.shared.b32 [%0], %1;" :: "r"(addr),
                 "r"(*(const uint32_t*)&v) : "memory");
}
__device__ __forceinline__ void split_f16(float x, __half& h, __half& l) {
    h = __float2half_rn(x);
    l = __float2half_rn(x - __half2float(h));
}

// ---------------------------------------------------------------------------
// Kernel 0: build A/B operand rows for tensor-core three_nn.
// d'(a,b) = |b|^2 - 2 a.b via 11 exact fp16xfp16 products:
//   A: [axh,axl,axh, ayh,ayl,ayh, azh,azl,azh, 1,1, 0...]
//   B: [-2bxh,-2bxh,-2bxl, -2byh,-2byh,-2byl, -2bzh,-2bzh,-2bzl, qh,ql, 0...]
// ---------------------------------------------------------------------------
__global__ void prep_nn_kernel(const float* __restrict__ xyz1,
                               const float* __restrict__ xyz2)
{
    const int i = blockIdx.x * 256 + threadIdx.x;
    if (i < TOTAL) {
        const float x = xyz1[3 * i], y = xyz1[3 * i + 1], z = xyz1[3 * i + 2];
        __half xh, xl, yh, yl, zh, zl;
        split_f16(x, xh, xl); split_f16(y, yh, yl); split_f16(z, zh, zl);
        __half r[16];
        r[0] = xh; r[1] = xl; r[2] = xh;
        r[3] = yh; r[4] = yl; r[5] = yh;
        r[6] = zh; r[7] = zl; r[8] = zh;
        r[9] = __float2half_rn(1.0f); r[10] = __float2half_rn(1.0f);
        r[11] = r[12] = r[13] = r[14] = r[15] = __float2half_rn(0.0f);
        *(uint4*)(g_Ann + (size_t)i * 16)     = ((const uint4*)r)[0];
        *(uint4*)(g_Ann + (size_t)i * 16 + 8) = ((const uint4*)r)[1];
    } else if (i < TOTAL + BATCH * MPTS) {
        const int j = i - TOTAL;
        const float x = xyz2[3 * j], y = xyz2[3 * j + 1], z = xyz2[3 * j + 2];
        const float q = x * x + y * y + z * z;
        __half xh, xl, yh, yl, zh, zl, qh, ql;
        split_f16(x, xh, xl); split_f16(y, yh, yl); split_f16(z, zh, zl);
        split_f16(q, qh, ql);
        __half r[16];
        r[0] = __float2half_rn(-2.0f * __half2float(xh));
        r[1] = r[0];
        r[2] = __float2half_rn(-2.0f * __half2float(xl));
        r[3] = __float2half_rn(-2.0f * __half2float(yh));
        r[4] = r[3];
        r[5] = __float2half_rn(-2.0f * __half2float(yl));
        r[6] = __float2half_rn(-2.0f * __half2float(zh));
        r[7] = r[6];
        r[8] = __float2half_rn(-2.0f * __half2float(zl));
        r[9] = qh; r[10] = ql;
        r[11] = r[12] = r[13] = r[14] = r[15] = __float2half_rn(0.0f);
        *(uint4*)(g_Bnn + (size_t)j * 16)     = ((const uint4*)r)[0];
        *(uint4*)(g_Bnn + (size_t)j * 16 + 8) = ((const uint4*)r)[1];
    }
}

// ---------------------------------------------------------------------------
// Kernel 1: tensor-core three_nn. 512 CTAs x 256 thr; CTA = 128 queries.
// Warp w owns query rows 16w..16w+15; streams all 4096 candidates through a
// 3-stage cp.async ring (512 cand/chunk). Per-thread register top-3, then
// smem merge + exact fp32 distance refinement for the 3 selected.
// ---------------------------------------------------------------------------
#define NN_CH   512
#define NN_NCHK (MPTS / NN_CH)      // 8
#define BROW    48                  // 32B payload + 16B pad (conflict-free)
#define NB_STG  (NN_CH * BROW)      // 24576
#define OFF_NA  0                   // A tile: 128 x 32B = 4096
#define OFF_NB  4096                // B ring: 3 x 24576 = 73728
#define OFF_NM  77824               // merge: 128 x 4 x 3 x 8B = 12288
#define NN_SMEM 90112

struct NNE { float d; int i; };

__device__ __forceinline__ void upd3(float d, int j,
                                     float& d0, float& d1, float& d2,
                                     int& i0, int& i1, int& i2) {
    if (d < d2) {
        if (d < d1) {
            d2 = d1; i2 = i1;
            if (d < d0) { d1 = d0; i1 = i0; d0 = d; i0 = j; }
            else        { d1 = d;  i1 = j; }
        } else {
            d2 = d; i2 = j;
        }
    }
}

__device__ __forceinline__ void nn_load_chunk(uint32_t dst, int batch, int c,
                                              int tid)
{
#pragma unroll
    for (int i = 0; i < 4; i++) {
        const int g = tid + i * 256;       // 0..1023
        const int row = g >> 1, piece = g & 1;
        cpa16(dst + row * BROW + piece * 16,
              g_Bnn + ((size_t)batch * MPTS + c * NN_CH + row) * 16
                    + piece * 8);
    }
}

__global__ __launch_bounds__(256) void three_nn_tc(
    const float* __restrict__ xyz1, const float* __restrict__ xyz2)
{
    extern __shared__ char smem[];
    const uint32_t sb = smem_to_u32(smem);
    const int tid = threadIdx.x;
    const int wid = tid >> 5;
    const int lane = tid & 31;
    const int gid = lane >> 2;
    const int tig = lane & 3;
    const int m0 = blockIdx.x * 128;
    const int batch = m0 >> 14;            // NPTS = 16384

    // prologue group 1: A tile (128 x 32B) + B chunk 0
    {
        const int row = tid >> 1, piece = tid & 1;
        cpa16(sb + OFF_NA + row * 32 + piece * 16,
              g_Ann + (size_t)(m0 + row) * 16 + piece * 8);
    }
    nn_load_chunk(sb + OFF_NB + 0 * NB_STG, batch, 0, tid);
    cpa_commit();
    nn_load_chunk(sb + OFF_NB + 1 * NB_STG, batch, 1, tid);
    cpa_commit();

    const uint32_t bRel = (uint32_t)((((lane >> 4) << 3) | (lane & 7)) * BROW
                                     + (((lane >> 3) & 1) << 4));

    uint32_t aF[4];
    float dA0 = 1e30f, dA1 = 1e30f, dA2 = 1e30f;
    float dB0 = 1e30f, dB1 = 1e30f, dB2 = 1e30f;
    int   iA0 = 0, iA1 = 0, iA2 = 0, iB0 = 0, iB1 = 0, iB2 = 0;

    for (int c = 0; c < NN_NCHK; c++) {
        cpa_wait<1>();
        __syncthreads();
        if (c == 0) {
            // warp's A fragment (constant for the whole kernel)
            const uint32_t aRel = (uint32_t)((lane & 15) * 32
                                             + ((lane >> 4) << 4));
            ldsm_x4(aF, sb + OFF_NA + wid * 512 + aRel);
        }
        if (c + 2 < NN_NCHK)
            nn_load_chunk(sb + OFF_NB + ((c + 2) % 3) * NB_STG, batch,
                          c + 2, tid);
        cpa_commit();

        const uint32_t sB = sb + OFF_NB + (c % 3) * NB_STG;
        const int jb = c * NN_CH + tig * 2;
#pragma unroll 4
        for (int nn = 0; nn < NN_CH / 16; nn++) {
            uint32_t bF[4];
            ldsm_x4(bF, sB + bRel + nn * (16 * BROW));
            float d[4], e[4];
            mma_f16z(d, aF, bF + 0);       // candidates nn*16 .. +7
            mma_f16z(e, aF, bF + 2);       // candidates nn*16+8 .. +15
            const int j0 = jb + nn * 16;   // cols 2*tig, 2*tig+1
            const int j1 = j0 + 8;
            // row gid
            const float mA = fminf(fminf(d[0], d[1]), fminf(e[0], e[1]));
            if (mA < dA2) {
                upd3(d[0], j0,     dA0, dA1, dA2, iA0, iA1, iA2);
                upd3(d[1], j0 + 1, dA0, dA1, dA2, iA0, iA1, iA2);
                upd3(e[0], j1,     dA0, dA1, dA2, iA0, iA1, iA2);
                upd3(e[1], j1 + 1, dA0, dA1, dA2, iA0, iA1, iA2);
            }
            // row gid + 8
            const float mB = fminf(fminf(d[2], d[3]), fminf(e[2], e[3]));
            if (mB < dB2) {
                upd3(d[2], j0,     dB0, dB1, dB2, iB0, iB1, iB2);
                upd3(d[3], j0 + 1, dB0, dB1, dB2, iB0, iB1, iB2);
                upd3(e[2], j1,     dB0, dB1, dB2, iB0, iB1, iB2);
                upd3(e[3], j1 + 1, dB0, dB1, dB2, iB0, iB1, iB2);
            }
        }
    }

    // merge: 4 threads (tig) hold partial top-3 per row
    NNE* me = (NNE*)(smem + OFF_NM);
    {
        const int rA = wid * 16 + gid;
        const int rB = rA + 8;
        NNE* ea = me + (rA * 4 + tig) * 3;
        ea[0].d = dA0; ea[0].i = iA0;
        ea[1].d = dA1; ea[1].i = iA1;
        ea[2].d = dA2; ea[2].i = iA2;
        NNE* eb = me + (rB * 4 + tig) * 3;
        eb[0].d = dB0; eb[0].i = iB0;
        eb[1].d = dB1; eb[1].i = iB1;
        eb[2].d = dB2; eb[2].i = iB2;
    }
    __syncthreads();

    if (tid < 128) {
        float d0 = 1e30f, d1 = 1e30f, d2 = 1e30f;
        int   i0 = 0, i1 = 0, i2 = 0;
        const NNE* e = me + tid * 12;
#pragma unroll
        for (int k = 0; k < 12; k++)
            upd3(e[k].d, e[k].i, d0, d1, d2, i0, i1, i2);

        // exact fp32 refinement of the 3 selected distances
        const int q = m0 + tid;
        const float* p1 = xyz1 + (size_t)q * 3;
        const float x = p1[0], y = p1[1], z = p1[2];
        const float* p2 = xyz2 + (size_t)batch * MPTS * 3;
        float dd[3];
        const int ii[3] = {i0, i1, i2};
#pragma unroll
        for (int k = 0; k < 3; k++) {
            const float* bpt = p2 + (size_t)ii[k] * 3;
            const float dx = x - bpt[0];
            const float dy = y - bpt[1];
            const float dz = z - bpt[2];
            dd[k] = fmaxf(dx * dx + dy * dy + dz * dz, 1e-10f);
        }
        const float r0 = 1.0f / dd[0];
        const float r1 = 1.0f / dd[1];
        const float r2 = 1.0f / dd[2];
        const float s = 1.0f / (r0 + r1 + r2);
        const size_t o = (size_t)q * 3;
        g_idx[o + 0] = i0; g_idx[o + 1] = i1; g_idx[o + 2] = i2;
        g_w[o + 0] = r0 * s; g_w[o + 1] = r1 * s; g_w[o + 2] = r2 * s;
    }
}

// ---------------------------------------------------------------------------
// Kernel 2: build X = concat(features1, interp(features2)) -> fp16.
// ---------------------------------------------------------------------------
__global__ __launch_bounds__(384) void build_x_kernel(
    const float* __restrict__ f1, const float* __restrict__ f2)
{
    const int tid = threadIdx.x;
    const int pt  = tid / 48;
    const int ch8 = (tid - pt * 48) * 8;
    const int p = blockIdx.x * 8 + pt;

    float v[8];
    if (ch8 < C1DIM) {
        const float* src = f1 + (size_t)p * C1DIM + ch8;
        const float4 a = *(const float4*)src;
        const float4 c = *(const float4*)(src + 4);
        v[0] = a.x; v[1] = a.y; v[2] = a.z; v[3] = a.w;
        v[4] = c.x; v[5] = c.y; v[6] = c.z; v[7] = c.w;
    } else {
        const int c = ch8 - C1DIM;
        const int bb = p >> 14;
        const size_t o = (size_t)p * 3;
        const int i0 = g_idx[o], i1 = g_idx[o + 1], i2 = g_idx[o + 2];
        const float w0 = g_w[o], w1 = g_w[o + 1], w2 = g_w[o + 2];
        const float* base = f2 + (size_t)bb * MPTS * C2DIM + c;
        const float* r0p = base + (size_t)i0 * C2DIM;
        const float* r1p = base + (size_t)i1 * C2DIM;
        const float* r2p = base + (size_t)i2 * C2DIM;
        const float4 a0 = *(const float4*)r0p;
        const float4 a1 = *(const float4*)(r0p + 4);
        const float4 b0 = *(const float4*)r1p;
        const float4 b1 = *(const float4*)(r1p + 4);
        const float4 c0 = *(const float4*)r2p;
        const float4 c1 = *(const float4*)(r2p + 4);
        v[0] = w0 * a0.x + w1 * b0.x + w2 * c0.x;
        v[1] = w0 * a0.y + w1 * b0.y + w2 * c0.y;
        v[2] = w0 * a0.z + w1 * b0.z + w2 * c0.z;
        v[3] = w0 * a0.w + w1 * b0.w + w2 * c0.w;
        v[4] = w0 * a1.x + w1 * b1.x + w2 * c1.x;
        v[5] = w0 * a1.y + w1 * b1.y + w2 * c1.y;
        v[6] = w0 * a1.z + w1 * b1.z + w2 * c1.z;
        v[7] = w0 * a1.w + w1 * b1.w + w2 * c1.w;
    }

    __half h[8];
#pragma unroll
    for (int k = 0; k < 8; k++) h[k] = __float2half_rn(v[k]);
    *(uint4*)(g_Xh + (size_t)p * CIN + ch8) = *(const uint4*)h;
}

// ---------------------------------------------------------------------------
// Kernel 2b: merged weight prep — transpose [K,N]->[N,K] + fp16
// ---------------------------------------------------------------------------
__global__ void prep_w_kernel(const float* __restrict__ W1,
                              const float* __restrict__ W2,
                              const float* __restrict__ W3)
{
    int i = blockIdx.x * 256 + threadIdx.x;
    if (i < H1DIM * CIN) {
        int n = i / CIN, k = i - n * CIN;
        g_W1h[i] = __float2half_rn(W1[(size_t)k * H1DIM + n]);
    } else if (i < H1DIM * CIN + H2DIM * H1DIM) {
        int j = i - H1DIM * CIN;
        int n = j / H1DIM, k = j - n * H1DIM;
        g_W2h[j] = __float2half_rn(W2[(size_t)k * H2DIM + n]);
    } else if (i < H1DIM * CIN + H2DIM * H1DIM + COUT * H2DIM) {
        int j = i - (H1DIM * CIN + H2DIM * H1DIM);
        int n = j / H2DIM, k = j - n * H2DIM;
        g_W3h[j] = __float2half_rn(W3[(size_t)k * COUT + n]);
    }
}

// ---------------------------------------------------------------------------
// Kernel 3: FUSED 3-layer MLP (proven R12 structure, unchanged).
// ---------------------------------------------------------------------------
#define SROW   144
#define SH     528
#define WSTG   36864
#define ASTG   18432
#define OFF_W  0
#define OFF_H1 73728
#define OFF_A  141312
#define OFF_H2 141312
#define FUSED_SMEM 208896
#define NCH1   (CIN / 64)     // 6
#define NCH2   (H1DIM / 64)   // 4
#define NCH3   (H2DIM / 64)   // 4

__device__ __forceinline__ void load_l1(uint32_t sb, int m0, int c, int tid) {
    const uint32_t adst = sb + OFF_A + (c & 1) * ASTG;
    const uint32_t wdst = sb + OFF_W + (c & 1) * WSTG;
    const int koff = c * 64;
#pragma unroll
    for (int i = 0; i < 2; i++) {
        const int g = tid + i * 512;
        const int row = g >> 3, piece = g & 7;
        cpa16(adst + row * SROW + piece * 16,
              g_Xh + (size_t)(m0 + row) * CIN + koff + piece * 8);
    }
#pragma unroll
    for (int i = 0; i < 4; i++) {
        const int g = tid + i * 512;
        const int row = g >> 3, piece = g & 7;
        cpa16(wdst + row * SROW + piece * 16,
              g_W1h + (size_t)row * CIN + koff + piece * 8);
    }
    cpa_commit();
}
__device__ __forceinline__ void load_w2(uint32_t sb, int c, int tid) {
    const uint32_t wdst = sb + OFF_W + (c & 1) * WSTG;
    const int koff = c * 64;
#pragma unroll
    for (int i = 0; i < 4; i++) {
        const int g = tid + i * 512;
        const int row = g >> 3, piece = g & 7;
        cpa16(wdst + row * SROW + piece * 16,
              g_W2h + (size_t)row * H1DIM + koff + piece * 8);
    }
    cpa_commit();
}
__device__ __forceinline__ void load_w3(uint32_t sb, int c, int tid) {
    const uint32_t wdst = sb + OFF_W + (c & 1) * WSTG;
    const int koff = c * 64;
#pragma unroll
    for (int i = 0; i < 2; i++) {
        const int g = tid + i * 512;
        const int row = g >> 3, piece = g & 7;
        cpa16(wdst + row * SROW + piece * 16,
              g_W3h + (size_t)row * H2DIM + koff + piece * 8);
    }
    cpa_commit();
}

__global__ __launch_bounds__(512, 1) void fused_mlp(
    const float* __restrict__ b1, const float* __restrict__ b2,
    const float* __restrict__ b3, float* __restrict__ out)
{
    extern __shared__ char smem[];
    const uint32_t sb = smem_to_u32(smem);
    const int tid = threadIdx.x;
    const int wid = tid >> 5;
    const int lane = tid & 31;
    const int gid = lane >> 2;
    const int tig = lane & 3;
    const int warp_m = wid >> 2;
    const int warp_n = wid & 3;
    const int m0 = blockIdx.x * 128;

    const int lane15 = lane & 15, laneHi = lane >> 4;
    const uint32_t aRel144 = (uint32_t)((warp_m * 32 + lane15) * SROW
                                        + (laneHi << 4));
    const uint32_t aRel528 = (uint32_t)((warp_m * 32 + lane15) * SH
                                        + (laneHi << 4));
    const uint32_t bRel64 = (uint32_t)((warp_n * 64 + (laneHi << 3)
                                        + (lane & 7)) * SROW
                                       + (((lane >> 3) & 1) << 4));
    const uint32_t bRel32 = (uint32_t)((warp_n * 32 + (laneHi << 3)
                                        + (lane & 7)) * SROW
                                       + (((lane >> 3) & 1) << 4));

    float acc[2][8][4];

    // ============================ Layer 1 ============================
#pragma unroll
    for (int t = 0; t < 2; t++)
#pragma unroll
        for (int nt = 0; nt < 8; nt++)
#pragma unroll
            for (int r = 0; r < 4; r++) acc[t][nt][r] = 0.0f;

    load_l1(sb, m0, 0, tid);
    load_l1(sb, m0, 1, tid);

    for (int c = 0; c < NCH1; c++) {
        if (c + 1 < NCH1) cpa_wait<1>(); else cpa_wait<0>();
        __syncthreads();
        const uint32_t sA = sb + OFF_A + (c & 1) * ASTG;
        const uint32_t sW = sb + OFF_W + (c & 1) * WSTG;
#pragma unroll
        for (int s = 0; s < 4; s++) {
            uint32_t aF[2][4], bF[4][4];
#pragma unroll
            for (int t = 0; t < 2; t++)
                ldsm_x4(aF[t], sA + aRel144 + t * (16 * SROW) + s * 32);
#pragma unroll
            for (int np = 0; np < 4; np++)
                ldsm_x4(bF[np], sW + bRel64 + np * (16 * SROW) + s * 32);
#pragma unroll
            for (int np = 0; np < 4; np++)
#pragma unroll
                for (int t = 0; t < 2; t++) {
                    mma_f16(acc[t][np * 2],     aF[t], bF[np] + 0);
                    mma_f16(acc[t][np * 2 + 1], aF[t], bF[np] + 2);
                }
        }
        __syncthreads();
        if (c + 2 < NCH1) load_l1(sb, m0, c + 2, tid);
    }

    load_w2(sb, 0, tid);
    load_w2(sb, 1, tid);

#pragma unroll
    for (int t = 0; t < 2; t++) {
        const int r0 = warp_m * 32 + t * 16 + gid;
#pragma unroll
        for (int nt = 0; nt < 8; nt++) {
            const int col = warp_n * 64 + nt * 8 + tig * 2;
            const float bv0 = __ldg(&b1[col]);
            const float bv1 = __ldg(&b1[col + 1]);
            const float v00 = fmaxf(acc[t][nt][0] + bv0, 0.0f);
            const float v01 = fmaxf(acc[t][nt][1] + bv1, 0.0f);
            const float v10 = fmaxf(acc[t][nt][2] + bv0, 0.0f);
            const float v11 = fmaxf(acc[t][nt][3] + bv1, 0.0f);
            sts_h2(sb + OFF_H1 + r0 * SH + col * 2,
                   __float2half_rn(v00), __float2half_rn(v01));
            sts_h2(sb + OFF_H1 + (r0 + 8) * SH + col * 2,
                   __float2half_rn(v10), __float2half_rn(v11));
        }
    }
    __syncthreads();

    // ============================ Layer 2 ============================
#pragma unroll
    for (int t = 0; t < 2; t++)
#pragma unroll
        for (int nt = 0; nt < 8; nt++)
#pragma unroll
            for (int r = 0; r < 4; r++) acc[t][nt][r] = 0.0f;

    for (int c = 0; c < NCH2; c++) {
        if (c + 1 < NCH2) cpa_wait<1>(); else cpa_wait<0>();
        __syncthreads();
        const uint32_t sW = sb + OFF_W + (c & 1) * WSTG;
        const uint32_t aBase = sb + OFF_H1 + aRel528 + c * 128;
#pragma unroll
        for (int s = 0; s < 4; s++) {
            uint32_t aF[2][4], bF[4][4];
#pragma unroll
            for (int t = 0; t < 2; t++)
                ldsm_x4(aF[t], aBase + t * (16 * SH) + s * 32);
#pragma unroll
            for (int np = 0; np < 4; np++)
                ldsm_x4(bF[np], sW + bRel64 + np * (16 * SROW) + s * 32);
#pragma unroll
            for (int np = 0; np < 4; np++)
#pragma unroll
                for (int t = 0; t < 2; t++) {
                    mma_f16(acc[t][np * 2],     aF[t], bF[np] + 0);
                    mma_f16(acc[t][np * 2 + 1], aF[t], bF[np] + 2);
                }
        }
        __syncthreads();
        if (c + 2 < NCH2) load_w2(sb, c + 2, tid);
    }

    load_w3(sb, 0, tid);
    load_w3(sb, 1, tid);

#pragma unroll
    for (int t = 0; t < 2; t++) {
        const int r0 = warp_m * 32 + t * 16 + gid;
#pragma unroll
        for (int nt = 0; nt < 8; nt++) {
            const int col = warp_n * 64 + nt * 8 + tig * 2;
            const float bv0 = __ldg(&b2[col]);
            const float bv1 = __ldg(&b2[col + 1]);
            const float v00 = fmaxf(acc[t][nt][0] + bv0, 0.0f);
            const float v01 = fmaxf(acc[t][nt][1] + bv1, 0.0f);
            const float v10 = fmaxf(acc[t][nt][2] + bv0, 0.0f);
            const float v11 = fmaxf(acc[t][nt][3] + bv1, 0.0f);
            sts_h2(sb + OFF_H2 + r0 * SH + col * 2,
                   __float2half_rn(v00), __float2half_rn(v01));
            sts_h2(sb + OFF_H2 + (r0 + 8) * SH + col * 2,
                   __float2half_rn(v10), __float2half_rn(v11));
        }
    }
    __syncthreads();

    // ============================ Layer 3 ============================
    float acc3[2][4][4];
#pragma unroll
    for (int t = 0; t < 2; t++)
#pragma unroll
        for (int nt = 0; nt < 4; nt++)
#pragma unroll
            for (int r = 0; r < 4; r++) acc3[t][nt][r] = 0.0f;

    for (int c = 0; c < NCH3; c++) {
        if (c + 1 < NCH3) cpa_wait<1>(); else cpa_wait<0>();
        __syncthreads();
        const uint32_t sW = sb + OFF_W + (c & 1) * WSTG;
        const uint32_t aBase = sb + OFF_H2 + aRel528 + c * 128;
#pragma unroll
        for (int s = 0; s < 4; s++) {
            uint32_t aF[2][4], bF[2][4];
#pragma unroll
            for (int t = 0; t < 2; t++)
                ldsm_x4(aF[t], aBase + t * (16 * SH) + s * 32);
#pragma unroll
            for (int np = 0; np < 2; np++)
                ldsm_x4(bF[np], sW + bRel32 + np * (16 * SROW) + s * 32);
#pragma unroll
            for (int np = 0; np < 2; np++)
#pragma unroll
                for (int t = 0; t < 2; t++) {
                    mma_f16(acc3[t][np * 2],     aF[t], bF[np] + 0);
                    mma_f16(acc3[t][np * 2 + 1], aF[t], bF[np] + 2);
                }
        }
        __syncthreads();
        if (c + 2 < NCH3) load_w3(sb, c + 2, tid);
    }

#pragma unroll
    for (int t = 0; t < 2; t++) {
        const int r0 = m0 + warp_m * 32 + t * 16 + gid;
        const int r1 = r0 + 8;
#pragma unroll
        for (int nt = 0; nt < 4; nt++) {
            const int col = warp_n * 32 + nt * 8 + tig * 2;
            const float bv0 = __ldg(&b3[col]);
            const float bv1 = __ldg(&b3[col + 1]);
            *(float2*)(out + (size_t)r0 * COUT + col) =
                make_float2(acc3[t][nt][0] + bv0, acc3[t][nt][1] + bv1);
            *(float2*)(out + (size_t)r1 * COUT + col) =
                make_float2(acc3[t][nt][2] + bv0, acc3[t][nt][3] + bv1);
        }
    }
}

// ---------------------------------------------------------------------------
// Launch
// ---------------------------------------------------------------------------
extern "C" void kernel_launch(void* const* d_in, const int* in_sizes, int n_in,
                              void* d_out, int out_size)
{
    const float* xyz1 = (const float*)d_in[0];
    const float* xyz2 = (const float*)d_in[1];
    const float* f1   = (const float*)d_in[2];
    const float* f2   = (const float*)d_in[3];
    const float* W1   = (const float*)d_in[4];
    const float* b1   = (const float*)d_in[5];
    const float* W2   = (const float*)d_in[6];
    const float* b2   = (const float*)d_in[7];
    const float* W3   = (const float*)d_in[8];
    const float* b3   = (const float*)d_in[9];
    float* out = (float*)d_out;

    cudaFuncSetAttribute(three_nn_tc,
                         cudaFuncAttributeMaxDynamicSharedMemorySize, NN_SMEM);
    cudaFuncSetAttribute(fused_mlp,
                         cudaFuncAttributeMaxDynamicSharedMemorySize,
                         FUSED_SMEM);

    const int prep_total = H1DIM * CIN + H2DIM * H1DIM + COUT * H2DIM;
    prep_w_kernel<<<(prep_total + 255) / 256, 256>>>(W1, W2, W3);

    const int nn_total = TOTAL + BATCH * MPTS;
    prep_nn_kernel<<<(nn_total + 255) / 256, 256>>>(xyz1, xyz2);

    three_nn_tc<<<TOTAL / 128, 256, NN_SMEM>>>(xyz1, xyz2);

    build_x_kernel<<<TOTAL / 8, 384>>>(f1, f2);

    fused_mlp<<<TOTAL / 128, 512, FUSED_SMEM>>>(b1, b2, b3, out);
}

// round 14
// speedup vs baseline: 1.1689x; 1.1689x over previous
#include <cuda_runtime.h>
#include <cuda_fp16.h>
#include <cstdint>

// Problem constants (fixed shapes for this dataset)
#define BATCH   4
#define NPTS    16384
#define MPTS    4096
#define C1DIM   128
#define C2DIM   256
#define CIN     384       // C1 + C2
#define H1DIM   256
#define H2DIM   256
#define COUT    128
#define TOTAL   (BATCH * NPTS)   // 65536 points

// ---------------------------------------------------------------------------
// Scratch (static device globals — no runtime allocation allowed)
// ---------------------------------------------------------------------------
__device__ int   g_idx[TOTAL * 3];
__device__ float g_w[TOTAL * 3];
__device__ __align__(256) __half g_W1h[H1DIM * CIN];
__device__ __align__(256) __half g_W2h[H2DIM * H1DIM];
__device__ __align__(256) __half g_W3h[COUT * H2DIM];

// ---------------------------------------------------------------------------
// Small helpers
// ---------------------------------------------------------------------------
__device__ __forceinline__ uint32_t smem_to_u32(const void* p) {
    uint32_t a;
    asm("{ .reg .u64 t; cvta.to.shared.u64 t, %1; cvt.u32.u64 %0, t; }"
        : "=r"(a) : "l"(p));
    return a;
}
__device__ __forceinline__ void cpa16(uint32_t dst, const void* src) {
    asm volatile("cp.async.cg.shared.global [%0], [%1], 16;"
                 :: "r"(dst), "l"(src));
}
__device__ __forceinline__ void cpa_commit() {
    asm volatile("cp.async.commit_group;" ::: "memory");
}
template <int N>
__device__ __forceinline__ void cpa_wait() {
    asm volatile("cp.async.wait_group %0;" :: "n"(N) : "memory");
}
__device__ __forceinline__ void ldsm_x4(uint32_t* r, uint32_t addr) {
    asm volatile("ldmatrix.sync.aligned.m8n8.x4.shared.b16 {%0,%1,%2,%3}, [%4];"
                 : "=r"(r[0]), "=r"(r[1]), "=r"(r[2]), "=r"(r[3]) : "r"(addr));
}
__device__ __forceinline__ void mma_f16(float* d, const uint32_t* a,
                                        const uint32_t* b) {
    asm("mma.sync.aligned.m16n8k16.row.col.f32.f16.f16.f32 "
        "{%0,%1,%2,%3}, {%4,%5,%6,%7}, {%8,%9}, {%0,%1,%2,%3};"
        : "+f"(d[0]), "+f"(d[1]), "+f"(d[2]), "+f"(d[3])
        : "r"(a[0]), "r"(a[1]), "r"(a[2]), "r"(a[3]), "r"(b[0]), "r"(b[1]));
}
__device__ __forceinline__ void sts_h2(uint32_t addr, __half a, __half b) {
    __half2 v = __halves2half2(a, b);
    asm volatile("st.shared.b32 [%0], %1;" :: "r"(addr),
                 "r"(*(const uint32_t*)&v) : "memory");
}
// packed f32x2 helpers
__device__ __forceinline__ unsigned long long pk2(float a, float b) {
    unsigned long long r;
    asm("mov.b64 %0, {%1, %2};" : "=l"(r)
        : "r"(__float_as_uint(a)), "r"(__float_as_uint(b)));
    return r;
}
__device__ __forceinline__ unsigned long long mul2(unsigned long long a,
                                                   unsigned long long b) {
    unsigned long long r;
    asm("mul.rn.f32x2 %0, %1, %2;" : "=l"(r) : "l"(a), "l"(b));
    return r;
}
__device__ __forceinline__ unsigned long long fma2(unsigned long long a,
                                                   unsigned long long b,
                                                   unsigned long long c) {
    unsigned long long r;
    asm("fma.rn.f32x2 %0, %1, %2, %3;" : "=l"(r) : "l"(a), "l"(b), "l"(c));
    return r;
}
__device__ __forceinline__ void unpk2(unsigned long long v, float& lo, float& hi) {
    uint32_t a, b;
    asm("mov.b64 {%0, %1}, %2;" : "=r"(a), "=r"(b) : "l"(v));
    lo = __uint_as_float(a);
    hi = __uint_as_float(b);
}

// ---------------------------------------------------------------------------
// Kernel 1: three_nn via d' = |b|^2 - 2 a.b (threshold-shifted; same ordering)
// — R12 proven version, reverted from the R13 tensor-core experiment.
// ---------------------------------------------------------------------------
__device__ __forceinline__ void upd3(float d, int j,
                                     float& d0, float& d1, float& d2,
                                     int& i0, int& i1, int& i2) {
    if (d < d2) {
        if (d < d1) {
            d2 = d1; i2 = i1;
            if (d < d0) { d1 = d0; i1 = i0; d0 = d; i0 = j; }
            else        { d1 = d;  i1 = j; }
        } else {
            d2 = d; i2 = j;
        }
    }
}

__global__ __launch_bounds__(256) void three_nn_kernel(
    const float* __restrict__ xyz1, const float* __restrict__ xyz2)
{
    extern __shared__ __align__(16) float s3[];
    float* sbx = s3;
    float* sby = s3 + MPTS;
    float* sbz = s3 + 2 * MPTS;
    float* sbq = s3 + 3 * MPTS;   // |b|^2

    const int b = blockIdx.y;
    const float* p2 = xyz2 + (size_t)b * MPTS * 3;
    for (int j = threadIdx.x; j < MPTS; j += 256) {
        const float bx = p2[3 * j + 0];
        const float by = p2[3 * j + 1];
        const float bz = p2[3 * j + 2];
        sbx[j] = bx; sby[j] = by; sbz[j] = bz;
        sbq[j] = bx * bx + by * by + bz * bz;
    }
    __syncthreads();

    const int n = blockIdx.x * 256 + threadIdx.x;
    const float* p1 = xyz1 + ((size_t)b * NPTS + n) * 3;
    const float x = p1[0], y = p1[1], z = p1[2];
    const unsigned long long x2 = pk2(x, x);
    const unsigned long long y2 = pk2(y, y);
    const unsigned long long z2 = pk2(z, z);
    const unsigned long long n2 = pk2(-2.0f, -2.0f);

    float d0 = 1e30f, d1 = 1e30f, d2 = 1e30f;
    int   i0 = 0, i1 = 0, i2 = 0;

    const ulonglong2* bxp = (const ulonglong2*)sbx;
    const ulonglong2* byp = (const ulonglong2*)sby;
    const ulonglong2* bzp = (const ulonglong2*)sbz;
    const ulonglong2* bqp = (const ulonglong2*)sbq;

#pragma unroll 2
    for (int p = 0; p < MPTS / 4; p++) {
        const ulonglong2 cx = bxp[p];
        const ulonglong2 cy = byp[p];
        const ulonglong2 cz = bzp[p];
        const ulonglong2 cq = bqp[p];
        unsigned long long t0 = mul2(x2, cx.x);
        t0 = fma2(y2, cy.x, t0);
        t0 = fma2(z2, cz.x, t0);
        const unsigned long long dp0 = fma2(n2, t0, cq.x);
        unsigned long long t1 = mul2(x2, cx.y);
        t1 = fma2(y2, cy.y, t1);
        t1 = fma2(z2, cz.y, t1);
        const unsigned long long dp1 = fma2(n2, t1, cq.y);
        float l0, h0, l1, h1;
        unpk2(dp0, l0, h0);
        unpk2(dp1, l1, h1);
        const float m = fminf(fminf(l0, h0), fminf(l1, h1));
        if (m < d2) {
            upd3(l0, 4 * p,     d0, d1, d2, i0, i1, i2);
            upd3(h0, 4 * p + 1, d0, d1, d2, i0, i1, i2);
            upd3(l1, 4 * p + 2, d0, d1, d2, i0, i1, i2);
            upd3(h1, 4 * p + 3, d0, d1, d2, i0, i1, i2);
        }
    }

    const float sqa = x * x + y * y + z * z;
    float r0 = 1.0f / fmaxf(d0 + sqa, 1e-10f);
    float r1 = 1.0f / fmaxf(d1 + sqa, 1e-10f);
    float r2 = 1.0f / fmaxf(d2 + sqa, 1e-10f);
    float s = 1.0f / (r0 + r1 + r2);

    size_t o = ((size_t)b * NPTS + n) * 3;
    g_idx[o + 0] = i0; g_idx[o + 1] = i1; g_idx[o + 2] = i2;
    g_w[o + 0] = r0 * s; g_w[o + 1] = r1 * s; g_w[o + 2] = r2 * s;
}

// ---------------------------------------------------------------------------
// Kernel 2b: merged weight prep — transpose [K,N]->[N,K] + fp16
// ---------------------------------------------------------------------------
__global__ void prep_w_kernel(const float* __restrict__ W1,
                              const float* __restrict__ W2,
                              const float* __restrict__ W3)
{
    int i = blockIdx.x * 256 + threadIdx.x;
    if (i < H1DIM * CIN) {
        int n = i / CIN, k = i - n * CIN;
        g_W1h[i] = __float2half_rn(W1[(size_t)k * H1DIM + n]);
    } else if (i < H1DIM * CIN + H2DIM * H1DIM) {
        int j = i - H1DIM * CIN;
        int n = j / H1DIM, k = j - n * H1DIM;
        g_W2h[j] = __float2half_rn(W2[(size_t)k * H2DIM + n]);
    } else if (i < H1DIM * CIN + H2DIM * H1DIM + COUT * H2DIM) {
        int j = i - (H1DIM * CIN + H2DIM * H1DIM);
        int n = j / H2DIM, k = j - n * H2DIM;
        g_W3h[j] = __float2half_rn(W3[(size_t)k * COUT + n]);
    }
}

// ---------------------------------------------------------------------------
// Kernel 3: FULLY FUSED build_x + 3-layer MLP.
// Each CTA builds its 128x384 X tile (concat + interp) directly in smem,
// then runs all 3 GEMM layers with H1/H2 in smem. No X/H gmem round-trips.
// 512 threads = 16 warps (4m x 4n).
//
// Smem map (bytes):
//   [0      .. 100352)  X tile: 128 rows x 784B (768 payload + 16 pad)
//   [100352 .. 174080)  W ring: 2 stages x 36864 (256 rows x 144B)
//   [0      .. 67584)   H1 (overlays X after L1 — guarded by barrier)
//   [0      .. 67584)   H2 (overlays H1 after L2 — guarded by barrier)
// ---------------------------------------------------------------------------
#define SROW   144
#define SH     528
#define XROW   784
#define WSTG   36864
#define OFF_X  0
#define OFF_W  100352
#define FUSED_SMEM 174080
#define NCH1   (CIN / 64)     // 6
#define NCH2   (H1DIM / 64)   // 4
#define NCH3   (H2DIM / 64)   // 4

__device__ __forceinline__ void load_w1(uint32_t sb, int c, int tid) {
    const uint32_t wdst = sb + OFF_W + (c & 1) * WSTG;
    const int koff = c * 64;
#pragma unroll
    for (int i = 0; i < 4; i++) {
        const int g = tid + i * 512;
        const int row = g >> 3, piece = g & 7;
        cpa16(wdst + row * SROW + piece * 16,
              g_W1h + (size_t)row * CIN + koff + piece * 8);
    }
    cpa_commit();
}
__device__ __forceinline__ void load_w2(uint32_t sb, int c, int tid) {
    const uint32_t wdst = sb + OFF_W + (c & 1) * WSTG;
    const int koff = c * 64;
#pragma unroll
    for (int i = 0; i < 4; i++) {
        const int g = tid + i * 512;
        const int row = g >> 3, piece = g & 7;
        cpa16(wdst + row * SROW + piece * 16,
              g_W2h + (size_t)row * H1DIM + koff + piece * 8);
    }
    cpa_commit();
}
__device__ __forceinline__ void load_w3(uint32_t sb, int c, int tid) {
    const uint32_t wdst = sb + OFF_W + (c & 1) * WSTG;
    const int koff = c * 64;
#pragma unroll
    for (int i = 0; i < 2; i++) {
        const int g = tid + i * 512;
        const int row = g >> 3, piece = g & 7;
        cpa16(wdst + row * SROW + piece * 16,
              g_W3h + (size_t)row * H2DIM + koff + piece * 8);
    }
    cpa_commit();
}

__global__ __launch_bounds__(512, 1) void fused_mlp(
    const float* __restrict__ f1, const float* __restrict__ f2,
    const float* __restrict__ b1, const float* __restrict__ b2,
    const float* __restrict__ b3, float* __restrict__ out)
{
    extern __shared__ char smem[];
    const uint32_t sb = smem_to_u32(smem);
    const int tid = threadIdx.x;
    const int wid = tid >> 5;
    const int lane = tid & 31;
    const int gid = lane >> 2;
    const int tig = lane & 3;
    const int warp_m = wid >> 2;
    const int warp_n = wid & 3;
    const int m0 = blockIdx.x * 128;

    const int lane15 = lane & 15, laneHi = lane >> 4;
    const uint32_t aRelX = (uint32_t)((warp_m * 32 + lane15) * XROW
                                      + (laneHi << 4));
    const uint32_t aRelH = (uint32_t)((warp_m * 32 + lane15) * SH
                                      + (laneHi << 4));
    const uint32_t bRel64 = (uint32_t)((warp_n * 64 + (laneHi << 3)
                                        + (lane & 7)) * SROW
                                       + (((lane >> 3) & 1) << 4));
    const uint32_t bRel32 = (uint32_t)((warp_n * 32 + (laneHi << 3)
                                        + (lane & 7)) * SROW
                                       + (((lane >> 3) & 1) << 4));

    // Prefetch W1 chunks 0,1 so the weight stream overlaps the X build.
    load_w1(sb, 0, tid);
    load_w1(sb, 1, tid);

    // ------------- build X tile (concat + interp) in smem -------------
    // 128 points x 48 channel-octets = 6144 slots; 12 per thread.
#pragma unroll
    for (int i = 0; i < 12; i++) {
        const int g = tid + i * 512;          // 0..6143
        const int pt = g / 48;
        const int ch8 = (g - pt * 48) * 8;
        const int p = m0 + pt;

        float v[8];
        if (ch8 < C1DIM) {
            const float* src = f1 + (size_t)p * C1DIM + ch8;
            const float4 a = *(const float4*)src;
            const float4 c = *(const float4*)(src + 4);
            v[0] = a.x; v[1] = a.y; v[2] = a.z; v[3] = a.w;
            v[4] = c.x; v[5] = c.y; v[6] = c.z; v[7] = c.w;
        } else {
            const int c = ch8 - C1DIM;
            const int bb = p >> 14;           // NPTS = 16384
            const size_t o = (size_t)p * 3;
            const int i0 = g_idx[o], i1 = g_idx[o + 1], i2 = g_idx[o + 2];
            const float w0 = g_w[o], w1 = g_w[o + 1], w2 = g_w[o + 2];
            const float* base = f2 + (size_t)bb * MPTS * C2DIM + c;
            const float* r0p = base + (size_t)i0 * C2DIM;
            const float* r1p = base + (size_t)i1 * C2DIM;
            const float* r2p = base + (size_t)i2 * C2DIM;
            const float4 a0 = *(const float4*)r0p;
            const float4 a1 = *(const float4*)(r0p + 4);
            const float4 b0 = *(const float4*)r1p;
            const float4 b1 = *(const float4*)(r1p + 4);
            const float4 c0 = *(const float4*)r2p;
            const float4 c1 = *(const float4*)(r2p + 4);
            v[0] = w0 * a0.x + w1 * b0.x + w2 * c0.x;
            v[1] = w0 * a0.y + w1 * b0.y + w2 * c0.y;
            v[2] = w0 * a0.z + w1 * b0.z + w2 * c0.z;
            v[3] = w0 * a0.w + w1 * b0.w + w2 * c0.w;
            v[4] = w0 * a1.x + w1 * b1.x + w2 * c1.x;
            v[5] = w0 * a1.y + w1 * b1.y + w2 * c1.y;
            v[6] = w0 * a1.z + w1 * b1.z + w2 * c1.z;
            v[7] = w0 * a1.w + w1 * b1.w + w2 * c1.w;
        }
        __half h[8];
#pragma unroll
        for (int k = 0; k < 8; k++) h[k] = __float2half_rn(v[k]);
        *(uint4*)(smem + OFF_X + pt * XROW + ch8 * 2) = *(const uint4*)h;
    }
    __syncthreads();   // X tile complete

    float acc[2][8][4];

    // ============================ Layer 1 ============================
#pragma unroll
    for (int t = 0; t < 2; t++)
#pragma unroll
        for (int nt = 0; nt < 8; nt++)
#pragma unroll
            for (int r = 0; r < 4; r++) acc[t][nt][r] = 0.0f;

    for (int c = 0; c < NCH1; c++) {
        if (c + 1 < NCH1) cpa_wait<1>(); else cpa_wait<0>();
        __syncthreads();
        const uint32_t sW = sb + OFF_W + (c & 1) * WSTG;
        const uint32_t aBase = sb + OFF_X + aRelX + c * 128;
#pragma unroll
        for (int s = 0; s < 4; s++) {
            uint32_t aF[2][4], bF[4][4];
#pragma unroll
            for (int t = 0; t < 2; t++)
                ldsm_x4(aF[t], aBase + t * (16 * XROW) + s * 32);
#pragma unroll
            for (int np = 0; np < 4; np++)
                ldsm_x4(bF[np], sW + bRel64 + np * (16 * SROW) + s * 32);
#pragma unroll
            for (int np = 0; np < 4; np++)
#pragma unroll
                for (int t = 0; t < 2; t++) {
                    mma_f16(acc[t][np * 2],     aF[t], bF[np] + 0);
                    mma_f16(acc[t][np * 2 + 1], aF[t], bF[np] + 2);
                }
        }
        __syncthreads();
        if (c + 2 < NCH1) load_w1(sb, c + 2, tid);
    }

    __syncthreads();   // all warps done reading X + W1 ring
    load_w2(sb, 0, tid);
    load_w2(sb, 1, tid);

    // L1 epilogue: bias + ReLU -> fp16 -> H1 (overlays X; safe post-barrier)
#pragma unroll
    for (int t = 0; t < 2; t++) {
        const int r0 = warp_m * 32 + t * 16 + gid;
#pragma unroll
        for (int nt = 0; nt < 8; nt++) {
            const int col = warp_n * 64 + nt * 8 + tig * 2;
            const float bv0 = __ldg(&b1[col]);
            const float bv1 = __ldg(&b1[col + 1]);
            const float v00 = fmaxf(acc[t][nt][0] + bv0, 0.0f);
            const float v01 = fmaxf(acc[t][nt][1] + bv1, 0.0f);
            const float v10 = fmaxf(acc[t][nt][2] + bv0, 0.0f);
            const float v11 = fmaxf(acc[t][nt][3] + bv1, 0.0f);
            sts_h2(sb + r0 * SH + col * 2,
                   __float2half_rn(v00), __float2half_rn(v01));
            sts_h2(sb + (r0 + 8) * SH + col * 2,
                   __float2half_rn(v10), __float2half_rn(v11));
        }
    }
    __syncthreads();   // H1 complete

    // ============================ Layer 2 ============================
#pragma unroll
    for (int t = 0; t < 2; t++)
#pragma unroll
        for (int nt = 0; nt < 8; nt++)
#pragma unroll
            for (int r = 0; r < 4; r++) acc[t][nt][r] = 0.0f;

    for (int c = 0; c < NCH2; c++) {
        if (c + 1 < NCH2) cpa_wait<1>(); else cpa_wait<0>();
        __syncthreads();
        const uint32_t sW = sb + OFF_W + (c & 1) * WSTG;
        const uint32_t aBase = sb + aRelH + c * 128;
#pragma unroll
        for (int s = 0; s < 4; s++) {
            uint32_t aF[2][4], bF[4][4];
#pragma unroll
            for (int t = 0; t < 2; t++)
                ldsm_x4(aF[t], aBase + t * (16 * SH) + s * 32);
#pragma unroll
            for (int np = 0; np < 4; np++)
                ldsm_x4(bF[np], sW + bRel64 + np * (16 * SROW) + s * 32);
#pragma unroll
            for (int np = 0; np < 4; np++)
#pragma unroll
                for (int t = 0; t < 2; t++) {
                    mma_f16(acc[t][np * 2],     aF[t], bF[np] + 0);
                    mma_f16(acc[t][np * 2 + 1], aF[t], bF[np] + 2);
                }
        }
        __syncthreads();
        if (c + 2 < NCH2) load_w2(sb, c + 2, tid);
    }

    __syncthreads();   // all warps done reading H1 + W2 ring
    load_w3(sb, 0, tid);
    load_w3(sb, 1, tid);

    // L2 epilogue: bias + ReLU -> fp16 -> H2 (overlays H1; safe post-barrier)
#pragma unroll
    for (int t = 0; t < 2; t++) {
        const int r0 = warp_m * 32 + t * 16 + gid;
#pragma unroll
        for (int nt = 0; nt < 8; nt++) {
            const int col = warp_n * 64 + nt * 8 + tig * 2;
            const float bv0 = __ldg(&b2[col]);
            const float bv1 = __ldg(&b2[col + 1]);
            const float v00 = fmaxf(acc[t][nt][0] + bv0, 0.0f);
            const float v01 = fmaxf(acc[t][nt][1] + bv1, 0.0f);
            const float v10 = fmaxf(acc[t][nt][2] + bv0, 0.0f);
            const float v11 = fmaxf(acc[t][nt][3] + bv1, 0.0f);
            sts_h2(sb + r0 * SH + col * 2,
                   __float2half_rn(v00), __float2half_rn(v01));
            sts_h2(sb + (r0 + 8) * SH + col * 2,
                   __float2half_rn(v10), __float2half_rn(v11));
        }
    }
    __syncthreads();   // H2 complete

    // ============================ Layer 3 ============================
    float acc3[2][4][4];
#pragma unroll
    for (int t = 0; t < 2; t++)
#pragma unroll
        for (int nt = 0; nt < 4; nt++)
#pragma unroll
            for (int r = 0; r < 4; r++) acc3[t][nt][r] = 0.0f;

    for (int c = 0; c < NCH3; c++) {
        if (c + 1 < NCH3) cpa_wait<1>(); else cpa_wait<0>();
        __syncthreads();
        const uint32_t sW = sb + OFF_W + (c & 1) * WSTG;
        const uint32_t aBase = sb + aRelH + c * 128;
#pragma unroll
        for (int s = 0; s < 4; s++) {
            uint32_t aF[2][4], bF[2][4];
#pragma unroll
            for (int t = 0; t < 2; t++)
                ldsm_x4(aF[t], aBase + t * (16 * SH) + s * 32);
#pragma unroll
            for (int np = 0; np < 2; np++)
                ldsm_x4(bF[np], sW + bRel32 + np * (16 * SROW) + s * 32);
#pragma unroll
            for (int np = 0; np < 2; np++)
#pragma unroll
                for (int t = 0; t < 2; t++) {
                    mma_f16(acc3[t][np * 2],     aF[t], bF[np] + 0);
                    mma_f16(acc3[t][np * 2 + 1], aF[t], bF[np] + 2);
                }
        }
        __syncthreads();
        if (c + 2 < NCH3) load_w3(sb, c + 2, tid);
    }

    // L3 epilogue: bias -> fp32 gmem
#pragma unroll
    for (int t = 0; t < 2; t++) {
        const int r0 = m0 + warp_m * 32 + t * 16 + gid;
        const int r1 = r0 + 8;
#pragma unroll
        for (int nt = 0; nt < 4; nt++) {
            const int col = warp_n * 32 + nt * 8 + tig * 2;
            const float bv0 = __ldg(&b3[col]);
            const float bv1 = __ldg(&b3[col + 1]);
            *(float2*)(out + (size_t)r0 * COUT + col) =
                make_float2(acc3[t][nt][0] + bv0, acc3[t][nt][1] + bv1);
            *(float2*)(out + (size_t)r1 * COUT + col) =
                make_float2(acc3[t][nt][2] + bv0, acc3[t][nt][3] + bv1);
        }
    }
}

// ---------------------------------------------------------------------------
// Launch
// ---------------------------------------------------------------------------
extern "C" void kernel_launch(void* const* d_in, const int* in_sizes, int n_in,
                              void* d_out, int out_size)
{
    const float* xyz1 = (const float*)d_in[0];
    const float* xyz2 = (const float*)d_in[1];
    const float* f1   = (const float*)d_in[2];
    const float* f2   = (const float*)d_in[3];
    const float* W1   = (const float*)d_in[4];
    const float* b1   = (const float*)d_in[5];
    const float* W2   = (const float*)d_in[6];
    const float* b2   = (const float*)d_in[7];
    const float* W3   = (const float*)d_in[8];
    const float* b3   = (const float*)d_in[9];
    float* out = (float*)d_out;

    const int nn_smem = 4 * MPTS * sizeof(float);   // 65536
    cudaFuncSetAttribute(three_nn_kernel,
                         cudaFuncAttributeMaxDynamicSharedMemorySize, nn_smem);
    cudaFuncSetAttribute(fused_mlp,
                         cudaFuncAttributeMaxDynamicSharedMemorySize,
                         FUSED_SMEM);

    const int prep_total = H1DIM * CIN + H2DIM * H1DIM + COUT * H2DIM;
    prep_w_kernel<<<(prep_total + 255) / 256, 256>>>(W1, W2, W3);

    dim3 g1(NPTS / 256, BATCH);
    three_nn_kernel<<<g1, 256, nn_smem>>>(xyz1, xyz2);

    fused_mlp<<<TOTAL / 128, 512, FUSED_SMEM>>>(f1, f2, b1, b2, b3, out);
}

// round 15
// speedup vs baseline: 1.1946x; 1.0220x over previous
#include <cuda_runtime.h>
#include <cuda_fp16.h>
#include <cstdint>

// Problem constants (fixed shapes for this dataset)
#define BATCH   4
#define NPTS    16384
#define MPTS    4096
#define C1DIM   128
#define C2DIM   256
#define CIN     384       // C1 + C2
#define H1DIM   256
#define H2DIM   256
#define COUT    128
#define TOTAL   (BATCH * NPTS)   // 65536 points
#define NSPLIT  4
#define CPS     (MPTS / NSPLIT)  // 1024 candidates per split

// ---------------------------------------------------------------------------
// Scratch (static device globals — no runtime allocation allowed)
// ---------------------------------------------------------------------------
__device__ int   g_idx[TOTAL * 3];
__device__ float g_w[TOTAL * 3];
__device__ float g_pd[(size_t)TOTAL * NSPLIT * 3];   // partial top-3 d'
__device__ int   g_pi[(size_t)TOTAL * NSPLIT * 3];   // partial top-3 idx
__device__ __align__(256) __half g_W1h[H1DIM * CIN];
__device__ __align__(256) __half g_W2h[H2DIM * H1DIM];
__device__ __align__(256) __half g_W3h[COUT * H2DIM];

// ---------------------------------------------------------------------------
// Small helpers
// ---------------------------------------------------------------------------
__device__ __forceinline__ uint32_t smem_to_u32(const void* p) {
    uint32_t a;
    asm("{ .reg .u64 t; cvta.to.shared.u64 t, %1; cvt.u32.u64 %0, t; }"
        : "=r"(a) : "l"(p));
    return a;
}
__device__ __forceinline__ void cpa16(uint32_t dst, const void* src) {
    asm volatile("cp.async.cg.shared.global [%0], [%1], 16;"
                 :: "r"(dst), "l"(src));
}
__device__ __forceinline__ void cpa_commit() {
    asm volatile("cp.async.commit_group;" ::: "memory");
}
template <int N>
__device__ __forceinline__ void cpa_wait() {
    asm volatile("cp.async.wait_group %0;" :: "n"(N) : "memory");
}
__device__ __forceinline__ void ldsm_x4(uint32_t* r, uint32_t addr) {
    asm volatile("ldmatrix.sync.aligned.m8n8.x4.shared.b16 {%0,%1,%2,%3}, [%4];"
                 : "=r"(r[0]), "=r"(r[1]), "=r"(r[2]), "=r"(r[3]) : "r"(addr));
}
__device__ __forceinline__ void mma_f16(float* d, const uint32_t* a,
                                        const uint32_t* b) {
    asm("mma.sync.aligned.m16n8k16.row.col.f32.f16.f16.f32 "
        "{%0,%1,%2,%3}, {%4,%5,%6,%7}, {%8,%9}, {%0,%1,%2,%3};"
        : "+f"(d[0]), "+f"(d[1]), "+f"(d[2]), "+f"(d[3])
        : "r"(a[0]), "r"(a[1]), "r"(a[2]), "r"(a[3]), "r"(b[0]), "r"(b[1]));
}
__device__ __forceinline__ void sts_h2(uint32_t addr, __half a, __half b) {
    __half2 v = __halves2half2(a, b);
    asm volatile("st.shared.b32 [%0], %1;" :: "r"(addr),
                 "r"(*(const uint32_t*)&v) : "memory");
}
// packed f32x2 helpers
__device__ __forceinline__ unsigned long long pk2(float a, float b) {
    unsigned long long r;
    asm("mov.b64 %0, {%1, %2};" : "=l"(r)
        : "r"(__float_as_uint(a)), "r"(__float_as_uint(b)));
    return r;
}
__device__ __forceinline__ unsigned long long fma2(unsigned long long a,
                                                   unsigned long long b,
                                                   unsigned long long c) {
    unsigned long long r;
    asm("fma.rn.f32x2 %0, %1, %2, %3;" : "=l"(r) : "l"(a), "l"(b), "l"(c));
    return r;
}
__device__ __forceinline__ void unpk2(unsigned long long v, float& lo, float& hi) {
    uint32_t a, b;
    asm("mov.b64 {%0, %1}, %2;" : "=r"(a), "=r"(b) : "l"(v));
    lo = __uint_as_float(a);
    hi = __uint_as_float(b);
}

__device__ __forceinline__ void upd3(float d, int j,
                                     float& d0, float& d1, float& d2,
                                     int& i0, int& i1, int& i2) {
    if (d < d2) {
        if (d < d1) {
            d2 = d1; i2 = i1;
            if (d < d0) { d1 = d0; i1 = i0; d0 = d; i0 = j; }
            else        { d1 = d;  i1 = j; }
        } else {
            d2 = d; i2 = j;
        }
    }
}

// ---------------------------------------------------------------------------
// Kernel 1a: partial three_nn. grid (NPTS/256, BATCH, NSPLIT); 256 threads.
// Each CTA scans CPS=1024 candidates with 16KB smem (high occupancy).
// d' = |b|^2 - 2 a.b tracked; smem holds (-2bx, -2by, -2bz, |b|^2).
// 8 candidates per iteration; one divergence guard per 8.
// ---------------------------------------------------------------------------
__global__ __launch_bounds__(256) void three_nn_part(
    const float* __restrict__ xyz1, const float* __restrict__ xyz2)
{
    __shared__ __align__(16) float smx[CPS];
    __shared__ __align__(16) float smy[CPS];
    __shared__ __align__(16) float smz[CPS];
    __shared__ __align__(16) float smq[CPS];

    const int b = blockIdx.y;
    const int zsp = blockIdx.z;
    const float* p2 = xyz2 + ((size_t)b * MPTS + zsp * CPS) * 3;
    for (int j = threadIdx.x; j < CPS; j += 256) {
        const float bx = p2[3 * j + 0];
        const float by = p2[3 * j + 1];
        const float bz = p2[3 * j + 2];
        smx[j] = -2.0f * bx;
        smy[j] = -2.0f * by;
        smz[j] = -2.0f * bz;
        smq[j] = bx * bx + by * by + bz * bz;
    }
    __syncthreads();

    const int q = b * NPTS + blockIdx.x * 256 + threadIdx.x;
    const float* p1 = xyz1 + (size_t)q * 3;
    const float x = p1[0], y = p1[1], z = p1[2];
    const unsigned long long x2 = pk2(x, x);
    const unsigned long long y2 = pk2(y, y);
    const unsigned long long z2 = pk2(z, z);

    float d0 = 1e30f, d1 = 1e30f, d2 = 1e30f;
    int   i0 = 0, i1 = 0, i2 = 0;

    const ulonglong2* mxp = (const ulonglong2*)smx;   // entry = 4 floats
    const ulonglong2* myp = (const ulonglong2*)smy;
    const ulonglong2* mzp = (const ulonglong2*)smz;
    const ulonglong2* mqp = (const ulonglong2*)smq;

#pragma unroll 2
    for (int p = 0; p < CPS / 8; p++) {
        const ulonglong2 cx0 = mxp[2 * p],     cx1 = mxp[2 * p + 1];
        const ulonglong2 cy0 = myp[2 * p],     cy1 = myp[2 * p + 1];
        const ulonglong2 cz0 = mzp[2 * p],     cz1 = mzp[2 * p + 1];
        const ulonglong2 cq0 = mqp[2 * p],     cq1 = mqp[2 * p + 1];

        unsigned long long t0 = fma2(x2, cx0.x, cq0.x);
        t0 = fma2(y2, cy0.x, t0);
        t0 = fma2(z2, cz0.x, t0);
        unsigned long long t1 = fma2(x2, cx0.y, cq0.y);
        t1 = fma2(y2, cy0.y, t1);
        t1 = fma2(z2, cz0.y, t1);
        unsigned long long t2 = fma2(x2, cx1.x, cq1.x);
        t2 = fma2(y2, cy1.x, t2);
        t2 = fma2(z2, cz1.x, t2);
        unsigned long long t3 = fma2(x2, cx1.y, cq1.y);
        t3 = fma2(y2, cy1.y, t3);
        t3 = fma2(z2, cz1.y, t3);

        float a0, b0, a1, b1, a2, b2, a3, b3;
        unpk2(t0, a0, b0);
        unpk2(t1, a1, b1);
        unpk2(t2, a2, b2);
        unpk2(t3, a3, b3);

        const float m = fminf(fminf(fminf(a0, b0), fminf(a1, b1)),
                              fminf(fminf(a2, b2), fminf(a3, b3)));
        if (m < d2) {
            const int j8 = 8 * p;
            upd3(a0, j8,     d0, d1, d2, i0, i1, i2);
            upd3(b0, j8 + 1, d0, d1, d2, i0, i1, i2);
            upd3(a1, j8 + 2, d0, d1, d2, i0, i1, i2);
            upd3(b1, j8 + 3, d0, d1, d2, i0, i1, i2);
            upd3(a2, j8 + 4, d0, d1, d2, i0, i1, i2);
            upd3(b2, j8 + 5, d0, d1, d2, i0, i1, i2);
            upd3(a3, j8 + 6, d0, d1, d2, i0, i1, i2);
            upd3(b3, j8 + 7, d0, d1, d2, i0, i1, i2);
        }
    }

    const size_t po = ((size_t)q * NSPLIT + zsp) * 3;
    g_pd[po + 0] = d0; g_pd[po + 1] = d1; g_pd[po + 2] = d2;
    g_pi[po + 0] = zsp * CPS + i0;
    g_pi[po + 1] = zsp * CPS + i1;
    g_pi[po + 2] = zsp * CPS + i2;
}

// ---------------------------------------------------------------------------
// Kernel 1b: merge partials + exact fp32 distance refinement -> idx, weights
// ---------------------------------------------------------------------------
__global__ __launch_bounds__(256) void three_nn_merge(
    const float* __restrict__ xyz1, const float* __restrict__ xyz2)
{
    const int q = blockIdx.x * 256 + threadIdx.x;

    float d0 = 1e30f, d1 = 1e30f, d2 = 1e30f;
    int   i0 = 0, i1 = 0, i2 = 0;
    const float* pd = g_pd + (size_t)q * NSPLIT * 3;
    const int*   pi = g_pi + (size_t)q * NSPLIT * 3;
#pragma unroll
    for (int k = 0; k < NSPLIT * 3; k++)
        upd3(pd[k], pi[k], d0, d1, d2, i0, i1, i2);

    const int batch = q >> 14;             // NPTS = 16384
    const float* p1 = xyz1 + (size_t)q * 3;
    const float x = p1[0], y = p1[1], z = p1[2];
    const float* p2 = xyz2 + (size_t)batch * MPTS * 3;
    const int ii[3] = {i0, i1, i2};
    float dd[3];
#pragma unroll
    for (int k = 0; k < 3; k++) {
        const float* bpt = p2 + (size_t)ii[k] * 3;
        const float dx = x - bpt[0];
        const float dy = y - bpt[1];
        const float dz = z - bpt[2];
        dd[k] = fmaxf(dx * dx + dy * dy + dz * dz, 1e-10f);
    }
    const float r0 = 1.0f / dd[0];
    const float r1 = 1.0f / dd[1];
    const float r2 = 1.0f / dd[2];
    const float s = 1.0f / (r0 + r1 + r2);
    const size_t o = (size_t)q * 3;
    g_idx[o + 0] = i0; g_idx[o + 1] = i1; g_idx[o + 2] = i2;
    g_w[o + 0] = r0 * s; g_w[o + 1] = r1 * s; g_w[o + 2] = r2 * s;
}

// ---------------------------------------------------------------------------
// Kernel 2b: merged weight prep — transpose [K,N]->[N,K] + fp16
// ---------------------------------------------------------------------------
__global__ void prep_w_kernel(const float* __restrict__ W1,
                              const float* __restrict__ W2,
                              const float* __restrict__ W3)
{
    int i = blockIdx.x * 256 + threadIdx.x;
    if (i < H1DIM * CIN) {
        int n = i / CIN, k = i - n * CIN;
        g_W1h[i] = __float2half_rn(W1[(size_t)k * H1DIM + n]);
    } else if (i < H1DIM * CIN + H2DIM * H1DIM) {
        int j = i - H1DIM * CIN;
        int n = j / H1DIM, k = j - n * H1DIM;
        g_W2h[j] = __float2half_rn(W2[(size_t)k * H2DIM + n]);
    } else if (i < H1DIM * CIN + H2DIM * H1DIM + COUT * H2DIM) {
        int j = i - (H1DIM * CIN + H2DIM * H1DIM);
        int n = j / H2DIM, k = j - n * H2DIM;
        g_W3h[j] = __float2half_rn(W3[(size_t)k * COUT + n]);
    }
}

// ---------------------------------------------------------------------------
// Kernel 3: FULLY FUSED build_x + 3-layer MLP (R14 proven, unchanged).
// ---------------------------------------------------------------------------
#define SROW   144
#define SH     528
#define XROW   784
#define WSTG   36864
#define OFF_X  0
#define OFF_W  100352
#define FUSED_SMEM 174080
#define NCH1   (CIN / 64)     // 6
#define NCH2   (H1DIM / 64)   // 4
#define NCH3   (H2DIM / 64)   // 4

__device__ __forceinline__ void load_w1(uint32_t sb, int c, int tid) {
    const uint32_t wdst = sb + OFF_W + (c & 1) * WSTG;
    const int koff = c * 64;
#pragma unroll
    for (int i = 0; i < 4; i++) {
        const int g = tid + i * 512;
        const int row = g >> 3, piece = g & 7;
        cpa16(wdst + row * SROW + piece * 16,
              g_W1h + (size_t)row * CIN + koff + piece * 8);
    }
    cpa_commit();
}
__device__ __forceinline__ void load_w2(uint32_t sb, int c, int tid) {
    const uint32_t wdst = sb + OFF_W + (c & 1) * WSTG;
    const int koff = c * 64;
#pragma unroll
    for (int i = 0; i < 4; i++) {
        const int g = tid + i * 512;
        const int row = g >> 3, piece = g & 7;
        cpa16(wdst + row * SROW + piece * 16,
              g_W2h + (size_t)row * H1DIM + koff + piece * 8);
    }
    cpa_commit();
}
__device__ __forceinline__ void load_w3(uint32_t sb, int c, int tid) {
    const uint32_t wdst = sb + OFF_W + (c & 1) * WSTG;
    const int koff = c * 64;
#pragma unroll
    for (int i = 0; i < 2; i++) {
        const int g = tid + i * 512;
        const int row = g >> 3, piece = g & 7;
        cpa16(wdst + row * SROW + piece * 16,
              g_W3h + (size_t)row * H2DIM + koff + piece * 8);
    }
    cpa_commit();
}

__global__ __launch_bounds__(512, 1) void fused_mlp(
    const float* __restrict__ f1, const float* __restrict__ f2,
    const float* __restrict__ b1, const float* __restrict__ b2,
    const float* __restrict__ b3, float* __restrict__ out)
{
    extern __shared__ char smem[];
    const uint32_t sb = smem_to_u32(smem);
    const int tid = threadIdx.x;
    const int wid = tid >> 5;
    const int lane = tid & 31;
    const int gid = lane >> 2;
    const int tig = lane & 3;
    const int warp_m = wid >> 2;
    const int warp_n = wid & 3;
    const int m0 = blockIdx.x * 128;

    const int lane15 = lane & 15, laneHi = lane >> 4;
    const uint32_t aRelX = (uint32_t)((warp_m * 32 + lane15) * XROW
                                      + (laneHi << 4));
    const uint32_t aRelH = (uint32_t)((warp_m * 32 + lane15) * SH
                                      + (laneHi << 4));
    const uint32_t bRel64 = (uint32_t)((warp_n * 64 + (laneHi << 3)
                                        + (lane & 7)) * SROW
                                       + (((lane >> 3) & 1) << 4));
    const uint32_t bRel32 = (uint32_t)((warp_n * 32 + (laneHi << 3)
                                        + (lane & 7)) * SROW
                                       + (((lane >> 3) & 1) << 4));

    load_w1(sb, 0, tid);
    load_w1(sb, 1, tid);

    // ------------- build X tile (concat + interp) in smem -------------
#pragma unroll
    for (int i = 0; i < 12; i++) {
        const int g = tid + i * 512;
        const int pt = g / 48;
        const int ch8 = (g - pt * 48) * 8;
        const int p = m0 + pt;

        float v[8];
        if (ch8 < C1DIM) {
            const float* src = f1 + (size_t)p * C1DIM + ch8;
            const float4 a = *(const float4*)src;
            const float4 c = *(const float4*)(src + 4);
            v[0] = a.x; v[1] = a.y; v[2] = a.z; v[3] = a.w;
            v[4] = c.x; v[5] = c.y; v[6] = c.z; v[7] = c.w;
        } else {
            const int c = ch8 - C1DIM;
            const int bb = p >> 14;
            const size_t o = (size_t)p * 3;
            const int i0 = g_idx[o], i1 = g_idx[o + 1], i2 = g_idx[o + 2];
            const float w0 = g_w[o], w1 = g_w[o + 1], w2 = g_w[o + 2];
            const float* base = f2 + (size_t)bb * MPTS * C2DIM + c;
            const float* r0p = base + (size_t)i0 * C2DIM;
            const float* r1p = base + (size_t)i1 * C2DIM;
            const float* r2p = base + (size_t)i2 * C2DIM;
            const float4 a0 = *(const float4*)r0p;
            const float4 a1 = *(const float4*)(r0p + 4);
            const float4 b0 = *(const float4*)r1p;
            const float4 b1 = *(const float4*)(r1p + 4);
            const float4 c0 = *(const float4*)r2p;
            const float4 c1 = *(const float4*)(r2p + 4);
            v[0] = w0 * a0.x + w1 * b0.x + w2 * c0.x;
            v[1] = w0 * a0.y + w1 * b0.y + w2 * c0.y;
            v[2] = w0 * a0.z + w1 * b0.z + w2 * c0.z;
            v[3] = w0 * a0.w + w1 * b0.w + w2 * c0.w;
            v[4] = w0 * a1.x + w1 * b1.x + w2 * c1.x;
            v[5] = w0 * a1.y + w1 * b1.y + w2 * c1.y;
            v[6] = w0 * a1.z + w1 * b1.z + w2 * c1.z;
            v[7] = w0 * a1.w + w1 * b1.w + w2 * c1.w;
        }
        __half h[8];
#pragma unroll
        for (int k = 0; k < 8; k++) h[k] = __float2half_rn(v[k]);
        *(uint4*)(smem + OFF_X + pt * XROW + ch8 * 2) = *(const uint4*)h;
    }
    __syncthreads();

    float acc[2][8][4];

    // ============================ Layer 1 ============================
#pragma unroll
    for (int t = 0; t < 2; t++)
#pragma unroll
        for (int nt = 0; nt < 8; nt++)
#pragma unroll
            for (int r = 0; r < 4; r++) acc[t][nt][r] = 0.0f;

    for (int c = 0; c < NCH1; c++) {
        if (c + 1 < NCH1) cpa_wait<1>(); else cpa_wait<0>();
        __syncthreads();
        const uint32_t sW = sb + OFF_W + (c & 1) * WSTG;
        const uint32_t aBase = sb + OFF_X + aRelX + c * 128;
#pragma unroll
        for (int s = 0; s < 4; s++) {
            uint32_t aF[2][4], bF[4][4];
#pragma unroll
            for (int t = 0; t < 2; t++)
                ldsm_x4(aF[t], aBase + t * (16 * XROW) + s * 32);
#pragma unroll
            for (int np = 0; np < 4; np++)
                ldsm_x4(bF[np], sW + bRel64 + np * (16 * SROW) + s * 32);
#pragma unroll
            for (int np = 0; np < 4; np++)
#pragma unroll
                for (int t = 0; t < 2; t++) {
                    mma_f16(acc[t][np * 2],     aF[t], bF[np] + 0);
                    mma_f16(acc[t][np * 2 + 1], aF[t], bF[np] + 2);
                }
        }
        __syncthreads();
        if (c + 2 < NCH1) load_w1(sb, c + 2, tid);
    }

    __syncthreads();
    load_w2(sb, 0, tid);
    load_w2(sb, 1, tid);

#pragma unroll
    for (int t = 0; t < 2; t++) {
        const int r0 = warp_m * 32 + t * 16 + gid;
#pragma unroll
        for (int nt = 0; nt < 8; nt++) {
            const int col = warp_n * 64 + nt * 8 + tig * 2;
            const float bv0 = __ldg(&b1[col]);
            const float bv1 = __ldg(&b1[col + 1]);
            const float v00 = fmaxf(acc[t][nt][0] + bv0, 0.0f);
            const float v01 = fmaxf(acc[t][nt][1] + bv1, 0.0f);
            const float v10 = fmaxf(acc[t][nt][2] + bv0, 0.0f);
            const float v11 = fmaxf(acc[t][nt][3] + bv1, 0.0f);
            sts_h2(sb + r0 * SH + col * 2,
                   __float2half_rn(v00), __float2half_rn(v01));
            sts_h2(sb + (r0 + 8) * SH + col * 2,
                   __float2half_rn(v10), __float2half_rn(v11));
        }
    }
    __syncthreads();

    // ============================ Layer 2 ============================
#pragma unroll
    for (int t = 0; t < 2; t++)
#pragma unroll
        for (int nt = 0; nt < 8; nt++)
#pragma unroll
            for (int r = 0; r < 4; r++) acc[t][nt][r] = 0.0f;

    for (int c = 0; c < NCH2; c++) {
        if (c + 1 < NCH2) cpa_wait<1>(); else cpa_wait<0>();
        __syncthreads();
        const uint32_t sW = sb + OFF_W + (c & 1) * WSTG;
        const uint32_t aBase = sb + aRelH + c * 128;
#pragma unroll
        for (int s = 0; s < 4; s++) {
            uint32_t aF[2][4], bF[4][4];
#pragma unroll
            for (int t = 0; t < 2; t++)
                ldsm_x4(aF[t], aBase + t * (16 * SH) + s * 32);
#pragma unroll
            for (int np = 0; np < 4; np++)
                ldsm_x4(bF[np], sW + bRel64 + np * (16 * SROW) + s * 32);
#pragma unroll
            for (int np = 0; np < 4; np++)
#pragma unroll
                for (int t = 0; t < 2; t++) {
                    mma_f16(acc[t][np * 2],     aF[t], bF[np] + 0);
                    mma_f16(acc[t][np * 2 + 1], aF[t], bF[np] + 2);
                }
        }
        __syncthreads();
        if (c + 2 < NCH2) load_w2(sb, c + 2, tid);
    }

    __syncthreads();
    load_w3(sb, 0, tid);
    load_w3(sb, 1, tid);

#pragma unroll
    for (int t = 0; t < 2; t++) {
        const int r0 = warp_m * 32 + t * 16 + gid;
#pragma unroll
        for (int nt = 0; nt < 8; nt++) {
            const int col = warp_n * 64 + nt * 8 + tig * 2;
            const float bv0 = __ldg(&b2[col]);
            const float bv1 = __ldg(&b2[col + 1]);
            const float v00 = fmaxf(acc[t][nt][0] + bv0, 0.0f);
            const float v01 = fmaxf(acc[t][nt][1] + bv1, 0.0f);
            const float v10 = fmaxf(acc[t][nt][2] + bv0, 0.0f);
            const float v11 = fmaxf(acc[t][nt][3] + bv1, 0.0f);
            sts_h2(sb + r0 * SH + col * 2,
                   __float2half_rn(v00), __float2half_rn(v01));
            sts_h2(sb + (r0 + 8) * SH + col * 2,
                   __float2half_rn(v10), __float2half_rn(v11));
        }
    }
    __syncthreads();

    // ============================ Layer 3 ============================
    float acc3[2][4][4];
#pragma unroll
    for (int t = 0; t < 2; t++)
#pragma unroll
        for (int nt = 0; nt < 4; nt++)
#pragma unroll
            for (int r = 0; r < 4; r++) acc3[t][nt][r] = 0.0f;

    for (int c = 0; c < NCH3; c++) {
        if (c + 1 < NCH3) cpa_wait<1>(); else cpa_wait<0>();
        __syncthreads();
        const uint32_t sW = sb + OFF_W + (c & 1) * WSTG;
        const uint32_t aBase = sb + aRelH + c * 128;
#pragma unroll
        for (int s = 0; s < 4; s++) {
            uint32_t aF[2][4], bF[2][4];
#pragma unroll
            for (int t = 0; t < 2; t++)
                ldsm_x4(aF[t], aBase + t * (16 * SH) + s * 32);
#pragma unroll
            for (int np = 0; np < 2; np++)
                ldsm_x4(bF[np], sW + bRel32 + np * (16 * SROW) + s * 32);
#pragma unroll
            for (int np = 0; np < 2; np++)
#pragma unroll
                for (int t = 0; t < 2; t++) {
                    mma_f16(acc3[t][np * 2],     aF[t], bF[np] + 0);
                    mma_f16(acc3[t][np * 2 + 1], aF[t], bF[np] + 2);
                }
        }
        __syncthreads();
        if (c + 2 < NCH3) load_w3(sb, c + 2, tid);
    }

#pragma unroll
    for (int t = 0; t < 2; t++) {
        const int r0 = m0 + warp_m * 32 + t * 16 + gid;
        const int r1 = r0 + 8;
#pragma unroll
        for (int nt = 0; nt < 4; nt++) {
            const int col = warp_n * 32 + nt * 8 + tig * 2;
            const float bv0 = __ldg(&b3[col]);
            const float bv1 = __ldg(&b3[col + 1]);
            *(float2*)(out + (size_t)r0 * COUT + col) =
                make_float2(acc3[t][nt][0] + bv0, acc3[t][nt][1] + bv1);
            *(float2*)(out + (size_t)r1 * COUT + col) =
                make_float2(acc3[t][nt][2] + bv0, acc3[t][nt][3] + bv1);
        }
    }
}

// ---------------------------------------------------------------------------
// Launch
// ---------------------------------------------------------------------------
extern "C" void kernel_launch(void* const* d_in, const int* in_sizes, int n_in,
                              void* d_out, int out_size)
{
    const float* xyz1 = (const float*)d_in[0];
    const float* xyz2 = (const float*)d_in[1];
    const float* f1   = (const float*)d_in[2];
    const float* f2   = (const float*)d_in[3];
    const float* W1   = (const float*)d_in[4];
    const float* b1   = (const float*)d_in[5];
    const float* W2   = (const float*)d_in[6];
    const float* b2   = (const float*)d_in[7];
    const float* W3   = (const float*)d_in[8];
    const float* b3   = (const float*)d_in[9];
    float* out = (float*)d_out;

    cudaFuncSetAttribute(fused_mlp,
                         cudaFuncAttributeMaxDynamicSharedMemorySize,
                         FUSED_SMEM);

    const int prep_total = H1DIM * CIN + H2DIM * H1DIM + COUT * H2DIM;
    prep_w_kernel<<<(prep_total + 255) / 256, 256>>>(W1, W2, W3);

    dim3 gp(NPTS / 256, BATCH, NSPLIT);
    three_nn_part<<<gp, 256>>>(xyz1, xyz2);
    three_nn_merge<<<TOTAL / 256, 256>>>(xyz1, xyz2);

    fused_mlp<<<TOTAL / 128, 512, FUSED_SMEM>>>(f1, f2, b1, b2, b3, out);
}

// round 16
// speedup vs baseline: 1.1963x; 1.0014x over previous
#include <cuda_runtime.h>
#include <cuda_fp16.h>
#include <cstdint>

// Problem constants (fixed shapes for this dataset)
#define BATCH   4
#define NPTS    16384
#define MPTS    4096
#define C1DIM   128
#define C2DIM   256
#define CIN     384       // C1 + C2
#define H1DIM   256
#define H2DIM   256
#define COUT    128
#define TOTAL   (BATCH * NPTS)   // 65536 points
#define NSPLIT  4
#define CPS     (MPTS / NSPLIT)  // 1024 candidates per split

// ---------------------------------------------------------------------------
// Scratch (static device globals — no runtime allocation allowed)
// ---------------------------------------------------------------------------
__device__ int   g_idx[TOTAL * 3];
__device__ float g_w[TOTAL * 3];
__device__ float g_pd[(size_t)TOTAL * NSPLIT * 3];   // partial top-3 d'
__device__ int   g_pi[(size_t)TOTAL * NSPLIT * 3];   // partial top-3 idx
__device__ __align__(256) __half g_W1h[H1DIM * CIN];
__device__ __align__(256) __half g_W2h[H2DIM * H1DIM];
__device__ __align__(256) __half g_W3h[COUT * H2DIM];

// ---------------------------------------------------------------------------
// Small helpers
// ---------------------------------------------------------------------------
__device__ __forceinline__ uint32_t smem_to_u32(const void* p) {
    uint32_t a;
    asm("{ .reg .u64 t; cvta.to.shared.u64 t, %1; cvt.u32.u64 %0, t; }"
        : "=r"(a) : "l"(p));
    return a;
}
__device__ __forceinline__ void cpa16(uint32_t dst, const void* src) {
    asm volatile("cp.async.cg.shared.global [%0], [%1], 16;"
                 :: "r"(dst), "l"(src));
}
__device__ __forceinline__ void cpa_commit() {
    asm volatile("cp.async.commit_group;" ::: "memory");
}
template <int N>
__device__ __forceinline__ void cpa_wait() {
    asm volatile("cp.async.wait_group %0;" :: "n"(N) : "memory");
}
__device__ __forceinline__ void ldsm_x4(uint32_t* r, uint32_t addr) {
    asm volatile("ldmatrix.sync.aligned.m8n8.x4.shared.b16 {%0,%1,%2,%3}, [%4];"
                 : "=r"(r[0]), "=r"(r[1]), "=r"(r[2]), "=r"(r[3]) : "r"(addr));
}
__device__ __forceinline__ void mma_f16(float* d, const uint32_t* a,
                                        const uint32_t* b) {
    asm("mma.sync.aligned.m16n8k16.row.col.f32.f16.f16.f32 "
        "{%0,%1,%2,%3}, {%4,%5,%6,%7}, {%8,%9}, {%0,%1,%2,%3};"
        : "+f"(d[0]), "+f"(d[1]), "+f"(d[2]), "+f"(d[3])
        : "r"(a[0]), "r"(a[1]), "r"(a[2]), "r"(a[3]), "r"(b[0]), "r"(b[1]));
}
__device__ __forceinline__ void sts_h2(uint32_t addr, __half a, __half b) {
    __half2 v = __halves2half2(a, b);
    asm volatile("st.shared.b32 [%0], %1;" :: "r"(addr),
                 "r"(*(const uint32_t*)&v) : "memory");
}
// packed f32x2 helpers
__device__ __forceinline__ unsigned long long pk2(float a, float b) {
    unsigned long long r;
    asm("mov.b64 %0, {%1, %2};" : "=l"(r)
        : "r"(__float_as_uint(a)), "r"(__float_as_uint(b)));
    return r;
}
__device__ __forceinline__ unsigned long long fma2(unsigned long long a,
                                                   unsigned long long b,
                                                   unsigned long long c) {
    unsigned long long r;
    asm("fma.rn.f32x2 %0, %1, %2, %3;" : "=l"(r) : "l"(a), "l"(b), "l"(c));
    return r;
}
__device__ __forceinline__ void unpk2(unsigned long long v, float& lo, float& hi) {
    uint32_t a, b;
    asm("mov.b64 {%0, %1}, %2;" : "=r"(a), "=r"(b) : "l"(v));
    lo = __uint_as_float(a);
    hi = __uint_as_float(b);
}

__device__ __forceinline__ void upd3(float d, int j,
                                     float& d0, float& d1, float& d2,
                                     int& i0, int& i1, int& i2) {
    if (d < d2) {
        if (d < d1) {
            d2 = d1; i2 = i1;
            if (d < d0) { d1 = d0; i1 = i0; d0 = d; i0 = j; }
            else        { d1 = d;  i1 = j; }
        } else {
            d2 = d; i2 = j;
        }
    }
}

// ---------------------------------------------------------------------------
// Kernel 1a: partial three_nn (R15 proven, unchanged).
// ---------------------------------------------------------------------------
__global__ __launch_bounds__(256) void three_nn_part(
    const float* __restrict__ xyz1, const float* __restrict__ xyz2)
{
    __shared__ __align__(16) float smx[CPS];
    __shared__ __align__(16) float smy[CPS];
    __shared__ __align__(16) float smz[CPS];
    __shared__ __align__(16) float smq[CPS];

    const int b = blockIdx.y;
    const int zsp = blockIdx.z;
    const float* p2 = xyz2 + ((size_t)b * MPTS + zsp * CPS) * 3;
    for (int j = threadIdx.x; j < CPS; j += 256) {
        const float bx = p2[3 * j + 0];
        const float by = p2[3 * j + 1];
        const float bz = p2[3 * j + 2];
        smx[j] = -2.0f * bx;
        smy[j] = -2.0f * by;
        smz[j] = -2.0f * bz;
        smq[j] = bx * bx + by * by + bz * bz;
    }
    __syncthreads();

    const int q = b * NPTS + blockIdx.x * 256 + threadIdx.x;
    const float* p1 = xyz1 + (size_t)q * 3;
    const float x = p1[0], y = p1[1], z = p1[2];
    const unsigned long long x2 = pk2(x, x);
    const unsigned long long y2 = pk2(y, y);
    const unsigned long long z2 = pk2(z, z);

    float d0 = 1e30f, d1 = 1e30f, d2 = 1e30f;
    int   i0 = 0, i1 = 0, i2 = 0;

    const ulonglong2* mxp = (const ulonglong2*)smx;
    const ulonglong2* myp = (const ulonglong2*)smy;
    const ulonglong2* mzp = (const ulonglong2*)smz;
    const ulonglong2* mqp = (const ulonglong2*)smq;

#pragma unroll 2
    for (int p = 0; p < CPS / 8; p++) {
        const ulonglong2 cx0 = mxp[2 * p],     cx1 = mxp[2 * p + 1];
        const ulonglong2 cy0 = myp[2 * p],     cy1 = myp[2 * p + 1];
        const ulonglong2 cz0 = mzp[2 * p],     cz1 = mzp[2 * p + 1];
        const ulonglong2 cq0 = mqp[2 * p],     cq1 = mqp[2 * p + 1];

        unsigned long long t0 = fma2(x2, cx0.x, cq0.x);
        t0 = fma2(y2, cy0.x, t0);
        t0 = fma2(z2, cz0.x, t0);
        unsigned long long t1 = fma2(x2, cx0.y, cq0.y);
        t1 = fma2(y2, cy0.y, t1);
        t1 = fma2(z2, cz0.y, t1);
        unsigned long long t2 = fma2(x2, cx1.x, cq1.x);
        t2 = fma2(y2, cy1.x, t2);
        t2 = fma2(z2, cz1.x, t2);
        unsigned long long t3 = fma2(x2, cx1.y, cq1.y);
        t3 = fma2(y2, cy1.y, t3);
        t3 = fma2(z2, cz1.y, t3);

        float a0, b0, a1, b1, a2, b2, a3, b3;
        unpk2(t0, a0, b0);
        unpk2(t1, a1, b1);
        unpk2(t2, a2, b2);
        unpk2(t3, a3, b3);

        const float m = fminf(fminf(fminf(a0, b0), fminf(a1, b1)),
                              fminf(fminf(a2, b2), fminf(a3, b3)));
        if (m < d2) {
            const int j8 = 8 * p;
            upd3(a0, j8,     d0, d1, d2, i0, i1, i2);
            upd3(b0, j8 + 1, d0, d1, d2, i0, i1, i2);
            upd3(a1, j8 + 2, d0, d1, d2, i0, i1, i2);
            upd3(b1, j8 + 3, d0, d1, d2, i0, i1, i2);
            upd3(a2, j8 + 4, d0, d1, d2, i0, i1, i2);
            upd3(b2, j8 + 5, d0, d1, d2, i0, i1, i2);
            upd3(a3, j8 + 6, d0, d1, d2, i0, i1, i2);
            upd3(b3, j8 + 7, d0, d1, d2, i0, i1, i2);
        }
    }

    const size_t po = ((size_t)q * NSPLIT + zsp) * 3;
    g_pd[po + 0] = d0; g_pd[po + 1] = d1; g_pd[po + 2] = d2;
    g_pi[po + 0] = zsp * CPS + i0;
    g_pi[po + 1] = zsp * CPS + i1;
    g_pi[po + 2] = zsp * CPS + i2;
}

// ---------------------------------------------------------------------------
// Kernel 1b: merge partials + exact fp32 refinement (R15 proven, unchanged).
// ---------------------------------------------------------------------------
__global__ __launch_bounds__(256) void three_nn_merge(
    const float* __restrict__ xyz1, const float* __restrict__ xyz2)
{
    const int q = blockIdx.x * 256 + threadIdx.x;

    float d0 = 1e30f, d1 = 1e30f, d2 = 1e30f;
    int   i0 = 0, i1 = 0, i2 = 0;
    const float* pd = g_pd + (size_t)q * NSPLIT * 3;
    const int*   pi = g_pi + (size_t)q * NSPLIT * 3;
#pragma unroll
    for (int k = 0; k < NSPLIT * 3; k++)
        upd3(pd[k], pi[k], d0, d1, d2, i0, i1, i2);

    const int batch = q >> 14;
    const float* p1 = xyz1 + (size_t)q * 3;
    const float x = p1[0], y = p1[1], z = p1[2];
    const float* p2 = xyz2 + (size_t)batch * MPTS * 3;
    const int ii[3] = {i0, i1, i2};
    float dd[3];
#pragma unroll
    for (int k = 0; k < 3; k++) {
        const float* bpt = p2 + (size_t)ii[k] * 3;
        const float dx = x - bpt[0];
        const float dy = y - bpt[1];
        const float dz = z - bpt[2];
        dd[k] = fmaxf(dx * dx + dy * dy + dz * dz, 1e-10f);
    }
    const float r0 = 1.0f / dd[0];
    const float r1 = 1.0f / dd[1];
    const float r2 = 1.0f / dd[2];
    const float s = 1.0f / (r0 + r1 + r2);
    const size_t o = (size_t)q * 3;
    g_idx[o + 0] = i0; g_idx[o + 1] = i1; g_idx[o + 2] = i2;
    g_w[o + 0] = r0 * s; g_w[o + 1] = r1 * s; g_w[o + 2] = r2 * s;
}

// ---------------------------------------------------------------------------
// Kernel 2b: merged weight prep — transpose [K,N]->[N,K] + fp16
// ---------------------------------------------------------------------------
__global__ void prep_w_kernel(const float* __restrict__ W1,
                              const float* __restrict__ W2,
                              const float* __restrict__ W3)
{
    int i = blockIdx.x * 256 + threadIdx.x;
    if (i < H1DIM * CIN) {
        int n = i / CIN, k = i - n * CIN;
        g_W1h[i] = __float2half_rn(W1[(size_t)k * H1DIM + n]);
    } else if (i < H1DIM * CIN + H2DIM * H1DIM) {
        int j = i - H1DIM * CIN;
        int n = j / H1DIM, k = j - n * H1DIM;
        g_W2h[j] = __float2half_rn(W2[(size_t)k * H2DIM + n]);
    } else if (i < H1DIM * CIN + H2DIM * H1DIM + COUT * H2DIM) {
        int j = i - (H1DIM * CIN + H2DIM * H1DIM);
        int n = j / H2DIM, k = j - n * H2DIM;
        g_W3h[j] = __float2half_rn(W3[(size_t)k * COUT + n]);
    }
}

// ---------------------------------------------------------------------------
// Kernel 3: FULLY FUSED build_x + 3-layer MLP — now BM=64 / 256 threads /
// BK=32 so TWO CTAs fit per SM (91.1KB smem, 128 regs).
// 8 warps (2m x 4n), warp tile 32x64 (L1/L2), 32x32 (L3).
//
// Smem map (bytes):
//   [0     .. 50176)  X tile: 64 rows x 784B
//   [50176 .. 91136)  W ring: 2 stages x 20480 (256 rows x 80B)
//   [0     .. 33792)  H1/H2 (64 rows x 528B; overlay X — barrier-guarded)
// ---------------------------------------------------------------------------
#define SROW   80
#define SH     528
#define XROW   784
#define WSTG   20480
#define OFF_X  0
#define OFF_W  50176
#define FUSED_SMEM 91136
#define NCH1   (CIN / 32)     // 12
#define NCH2   (H1DIM / 32)   // 8
#define NCH3   (H2DIM / 32)   // 8

__device__ __forceinline__ void load_w1(uint32_t sb, int c, int tid) {
    const uint32_t wdst = sb + OFF_W + (c & 1) * WSTG;
    const int koff = c * 32;
#pragma unroll
    for (int i = 0; i < 4; i++) {                 // 256 rows x 4 pieces
        const int g = tid + i * 256;
        const int row = g >> 2, piece = g & 3;
        cpa16(wdst + row * SROW + piece * 16,
              g_W1h + (size_t)row * CIN + koff + piece * 8);
    }
    cpa_commit();
}
__device__ __forceinline__ void load_w2(uint32_t sb, int c, int tid) {
    const uint32_t wdst = sb + OFF_W + (c & 1) * WSTG;
    const int koff = c * 32;
#pragma unroll
    for (int i = 0; i < 4; i++) {
        const int g = tid + i * 256;
        const int row = g >> 2, piece = g & 3;
        cpa16(wdst + row * SROW + piece * 16,
              g_W2h + (size_t)row * H1DIM + koff + piece * 8);
    }
    cpa_commit();
}
__device__ __forceinline__ void load_w3(uint32_t sb, int c, int tid) {
    const uint32_t wdst = sb + OFF_W + (c & 1) * WSTG;
    const int koff = c * 32;
#pragma unroll
    for (int i = 0; i < 2; i++) {                 // 128 rows x 4 pieces
        const int g = tid + i * 256;
        const int row = g >> 2, piece = g & 3;
        cpa16(wdst + row * SROW + piece * 16,
              g_W3h + (size_t)row * H2DIM + koff + piece * 8);
    }
    cpa_commit();
}

__global__ __launch_bounds__(256, 2) void fused_mlp(
    const float* __restrict__ f1, const float* __restrict__ f2,
    const float* __restrict__ b1, const float* __restrict__ b2,
    const float* __restrict__ b3, float* __restrict__ out)
{
    extern __shared__ char smem[];
    const uint32_t sb = smem_to_u32(smem);
    const int tid = threadIdx.x;
    const int wid = tid >> 5;
    const int lane = tid & 31;
    const int gid = lane >> 2;
    const int tig = lane & 3;
    const int warp_m = wid >> 2;          // 0..1
    const int warp_n = wid & 3;           // 0..3
    const int m0 = blockIdx.x * 64;

    const int lane15 = lane & 15, laneHi = lane >> 4;
    const uint32_t aRelX = (uint32_t)((warp_m * 32 + lane15) * XROW
                                      + (laneHi << 4));
    const uint32_t aRelH = (uint32_t)((warp_m * 32 + lane15) * SH
                                      + (laneHi << 4));
    const uint32_t bRel64 = (uint32_t)((warp_n * 64 + (laneHi << 3)
                                        + (lane & 7)) * SROW
                                       + (((lane >> 3) & 1) << 4));
    const uint32_t bRel32 = (uint32_t)((warp_n * 32 + (laneHi << 3)
                                        + (lane & 7)) * SROW
                                       + (((lane >> 3) & 1) << 4));

    load_w1(sb, 0, tid);
    load_w1(sb, 1, tid);

    // ------------- build X tile (concat + interp) in smem -------------
    // 64 points x 48 channel-octets = 3072 slots; 12 per thread.
#pragma unroll
    for (int i = 0; i < 12; i++) {
        const int g = tid + i * 256;
        const int pt = g / 48;
        const int ch8 = (g - pt * 48) * 8;
        const int p = m0 + pt;

        float v[8];
        if (ch8 < C1DIM) {
            const float* src = f1 + (size_t)p * C1DIM + ch8;
            const float4 a = *(const float4*)src;
            const float4 c = *(const float4*)(src + 4);
            v[0] = a.x; v[1] = a.y; v[2] = a.z; v[3] = a.w;
            v[4] = c.x; v[5] = c.y; v[6] = c.z; v[7] = c.w;
        } else {
            const int c = ch8 - C1DIM;
            const int bb = p >> 14;
            const size_t o = (size_t)p * 3;
            const int i0 = g_idx[o], i1 = g_idx[o + 1], i2 = g_idx[o + 2];
            const float w0 = g_w[o], w1 = g_w[o + 1], w2 = g_w[o + 2];
            const float* base = f2 + (size_t)bb * MPTS * C2DIM + c;
            const float* r0p = base + (size_t)i0 * C2DIM;
            const float* r1p = base + (size_t)i1 * C2DIM;
            const float* r2p = base + (size_t)i2 * C2DIM;
            const float4 a0 = *(const float4*)r0p;
            const float4 a1 = *(const float4*)(r0p + 4);
            const float4 b0 = *(const float4*)r1p;
            const float4 b1 = *(const float4*)(r1p + 4);
            const float4 c0 = *(const float4*)r2p;
            const float4 c1 = *(const float4*)(r2p + 4);
            v[0] = w0 * a0.x + w1 * b0.x + w2 * c0.x;
            v[1] = w0 * a0.y + w1 * b0.y + w2 * c0.y;
            v[2] = w0 * a0.z + w1 * b0.z + w2 * c0.z;
            v[3] = w0 * a0.w + w1 * b0.w + w2 * c0.w;
            v[4] = w0 * a1.x + w1 * b1.x + w2 * c1.x;
            v[5] = w0 * a1.y + w1 * b1.y + w2 * c1.y;
            v[6] = w0 * a1.z + w1 * b1.z + w2 * c1.z;
            v[7] = w0 * a1.w + w1 * b1.w + w2 * c1.w;
        }
        __half h[8];
#pragma unroll
        for (int k = 0; k < 8; k++) h[k] = __float2half_rn(v[k]);
        *(uint4*)(smem + OFF_X + pt * XROW + ch8 * 2) = *(const uint4*)h;
    }
    __syncthreads();

    float acc[2][8][4];

    // ============================ Layer 1 ============================
#pragma unroll
    for (int t = 0; t < 2; t++)
#pragma unroll
        for (int nt = 0; nt < 8; nt++)
#pragma unroll
            for (int r = 0; r < 4; r++) acc[t][nt][r] = 0.0f;

    for (int c = 0; c < NCH1; c++) {
        if (c + 1 < NCH1) cpa_wait<1>(); else cpa_wait<0>();
        __syncthreads();
        const uint32_t sW = sb + OFF_W + (c & 1) * WSTG;
        const uint32_t aBase = sb + OFF_X + aRelX + c * 64;
#pragma unroll
        for (int s = 0; s < 2; s++) {
            uint32_t aF[2][4], bF[4][4];
#pragma unroll
            for (int t = 0; t < 2; t++)
                ldsm_x4(aF[t], aBase + t * (16 * XROW) + s * 32);
#pragma unroll
            for (int np = 0; np < 4; np++)
                ldsm_x4(bF[np], sW + bRel64 + np * (16 * SROW) + s * 32);
#pragma unroll
            for (int np = 0; np < 4; np++)
#pragma unroll
                for (int t = 0; t < 2; t++) {
                    mma_f16(acc[t][np * 2],     aF[t], bF[np] + 0);
                    mma_f16(acc[t][np * 2 + 1], aF[t], bF[np] + 2);
                }
        }
        __syncthreads();
        if (c + 2 < NCH1) load_w1(sb, c + 2, tid);
    }

    __syncthreads();   // all warps done reading X + W1 ring
    load_w2(sb, 0, tid);
    load_w2(sb, 1, tid);

    // L1 epilogue: bias + ReLU -> fp16 -> H1 (overlays X; safe post-barrier)
#pragma unroll
    for (int t = 0; t < 2; t++) {
        const int r0 = warp_m * 32 + t * 16 + gid;
#pragma unroll
        for (int nt = 0; nt < 8; nt++) {
            const int col = warp_n * 64 + nt * 8 + tig * 2;
            const float bv0 = __ldg(&b1[col]);
            const float bv1 = __ldg(&b1[col + 1]);
            const float v00 = fmaxf(acc[t][nt][0] + bv0, 0.0f);
            const float v01 = fmaxf(acc[t][nt][1] + bv1, 0.0f);
            const float v10 = fmaxf(acc[t][nt][2] + bv0, 0.0f);
            const float v11 = fmaxf(acc[t][nt][3] + bv1, 0.0f);
            sts_h2(sb + r0 * SH + col * 2,
                   __float2half_rn(v00), __float2half_rn(v01));
            sts_h2(sb + (r0 + 8) * SH + col * 2,
                   __float2half_rn(v10), __float2half_rn(v11));
        }
    }
    __syncthreads();   // H1 complete

    // ============================ Layer 2 ============================
#pragma unroll
    for (int t = 0; t < 2; t++)
#pragma unroll
        for (int nt = 0; nt < 8; nt++)
#pragma unroll
            for (int r = 0; r < 4; r++) acc[t][nt][r] = 0.0f;

    for (int c = 0; c < NCH2; c++) {
        if (c + 1 < NCH2) cpa_wait<1>(); else cpa_wait<0>();
        __syncthreads();
        const uint32_t sW = sb + OFF_W + (c & 1) * WSTG;
        const uint32_t aBase = sb + aRelH + c * 64;
#pragma unroll
        for (int s = 0; s < 2; s++) {
            uint32_t aF[2][4], bF[4][4];
#pragma unroll
            for (int t = 0; t < 2; t++)
                ldsm_x4(aF[t], aBase + t * (16 * SH) + s * 32);
#pragma unroll
            for (int np = 0; np < 4; np++)
                ldsm_x4(bF[np], sW + bRel64 + np * (16 * SROW) + s * 32);
#pragma unroll
            for (int np = 0; np < 4; np++)
#pragma unroll
                for (int t = 0; t < 2; t++) {
                    mma_f16(acc[t][np * 2],     aF[t], bF[np] + 0);
                    mma_f16(acc[t][np * 2 + 1], aF[t], bF[np] + 2);
                }
        }
        __syncthreads();
        if (c + 2 < NCH2) load_w2(sb, c + 2, tid);
    }

    __syncthreads();   // all warps done reading H1 + W2 ring
    load_w3(sb, 0, tid);
    load_w3(sb, 1, tid);

    // L2 epilogue: bias + ReLU -> fp16 -> H2 (overlays H1; safe post-barrier)
#pragma unroll
    for (int t = 0; t < 2; t++) {
        const int r0 = warp_m * 32 + t * 16 + gid;
#pragma unroll
        for (int nt = 0; nt < 8; nt++) {
            const int col = warp_n * 64 + nt * 8 + tig * 2;
            const float bv0 = __ldg(&b2[col]);
            const float bv1 = __ldg(&b2[col + 1]);
            const float v00 = fmaxf(acc[t][nt][0] + bv0, 0.0f);
            const float v01 = fmaxf(acc[t][nt][1] + bv1, 0.0f);
            const float v10 = fmaxf(acc[t][nt][2] + bv0, 0.0f);
            const float v11 = fmaxf(acc[t][nt][3] + bv1, 0.0f);
            sts_h2(sb + r0 * SH + col * 2,
                   __float2half_rn(v00), __float2half_rn(v01));
            sts_h2(sb + (r0 + 8) * SH + col * 2,
                   __float2half_rn(v10), __float2half_rn(v11));
        }
    }
    __syncthreads();   // H2 complete

    // ============================ Layer 3 ============================
    float acc3[2][4][4];
#pragma unroll
    for (int t = 0; t < 2; t++)
#pragma unroll
        for (int nt = 0; nt < 4; nt++)
#pragma unroll
            for (int r = 0; r < 4; r++) acc3[t][nt][r] = 0.0f;

    for (int c = 0; c < NCH3; c++) {
        if (c + 1 < NCH3) cpa_wait<1>(); else cpa_wait<0>();
        __syncthreads();
        const uint32_t sW = sb + OFF_W + (c & 1) * WSTG;
        const uint32_t aBase = sb + aRelH + c * 64;
#pragma unroll
        for (int s = 0; s < 2; s++) {
            uint32_t aF[2][4], bF[2][4];
#pragma unroll
            for (int t = 0; t < 2; t++)
                ldsm_x4(aF[t], aBase + t * (16 * SH) + s * 32);
#pragma unroll
            for (int np = 0; np < 2; np++)
                ldsm_x4(bF[np], sW + bRel32 + np * (16 * SROW) + s * 32);
#pragma unroll
            for (int np = 0; np < 2; np++)
#pragma unroll
                for (int t = 0; t < 2; t++) {
                    mma_f16(acc3[t][np * 2],     aF[t], bF[np] + 0);
                    mma_f16(acc3[t][np * 2 + 1], aF[t], bF[np] + 2);
                }
        }
        __syncthreads();
        if (c + 2 < NCH3) load_w3(sb, c + 2, tid);
    }

    // L3 epilogue: bias -> fp32 gmem
#pragma unroll
    for (int t = 0; t < 2; t++) {
        const int r0 = m0 + warp_m * 32 + t * 16 + gid;
        const int r1 = r0 + 8;
#pragma unroll
        for (int nt = 0; nt < 4; nt++) {
            const int col = warp_n * 32 + nt * 8 + tig * 2;
            const float bv0 = __ldg(&b3[col]);
            const float bv1 = __ldg(&b3[col + 1]);
            *(float2*)(out + (size_t)r0 * COUT + col) =
                make_float2(acc3[t][nt][0] + bv0, acc3[t][nt][1] + bv1);
            *(float2*)(out + (size_t)r1 * COUT + col) =
                make_float2(acc3[t][nt][2] + bv0, acc3[t][nt][3] + bv1);
        }
    }
}

// ---------------------------------------------------------------------------
// Launch
// ---------------------------------------------------------------------------
extern "C" void kernel_launch(void* const* d_in, const int* in_sizes, int n_in,
                              void* d_out, int out_size)
{
    const float* xyz1 = (const float*)d_in[0];
    const float* xyz2 = (const float*)d_in[1];
    const float* f1   = (const float*)d_in[2];
    const float* f2   = (const float*)d_in[3];
    const float* W1   = (const float*)d_in[4];
    const float* b1   = (const float*)d_in[5];
    const float* W2   = (const float*)d_in[6];
    const float* b2   = (const float*)d_in[7];
    const float* W3   = (const float*)d_in[8];
    const float* b3   = (const float*)d_in[9];
    float* out = (float*)d_out;

    cudaFuncSetAttribute(fused_mlp,
                         cudaFuncAttributeMaxDynamicSharedMemorySize,
                         FUSED_SMEM);

    const int prep_total = H1DIM * CIN + H2DIM * H1DIM + COUT * H2DIM;
    prep_w_kernel<<<(prep_total + 255) / 256, 256>>>(W1, W2, W3);

    dim3 gp(NPTS / 256, BATCH, NSPLIT);
    three_nn_part<<<gp, 256>>>(xyz1, xyz2);
    three_nn_merge<<<TOTAL / 256, 256>>>(xyz1, xyz2);

    fused_mlp<<<TOTAL / 64, 256, FUSED_SMEM>>>(f1, f2, b1, b2, b3, out);
}